// round 2
// baseline (speedup 1.0000x reference)
#include <cuda_runtime.h>

#define LN_EPS 1e-5f

// ---- scratch ----
__device__ float g_s1[64*128*1024];
__device__ float g_s2[64*128*256];
__device__ float g_y3[64*192*256];
__device__ float g_kp[64*32*128];
__device__ float g_vp[64*32*192];
__device__ float g_gT[2][16384];

__device__ __forceinline__ float tanh_fast(float x){
    float y; asm("tanh.approx.f32 %0, %1;" : "=f"(y) : "f"(x)); return y;
}

// ---- prep: transpose gammas ----
__global__ void prep_kernel(const float* __restrict__ g1, const float* __restrict__ g2){
    int bwhich = blockIdx.x >> 6;
    int e = ((blockIdx.x & 63) << 8) + threadIdx.x;
    const float* g = bwhich ? g2 : g1;
    int d = e >> 7, c = e & 127;
    g_gT[bwhich][c*128 + d] = g[e];
}

// ---- conv1: 3->128, 5x5, s2, p2 (64x64 -> 32x32). grid (64,4,2), 256 thr ----
__global__ void conv1_kernel(const float* __restrict__ x, const float* __restrict__ w,
                             const float* __restrict__ b){
    __shared__ float sw[4800];        // 64 co x 75
    __shared__ float sin_[3885];      // 3 x 35 x 37
    int bp = blockIdx.x, tile = blockIdx.y, z = blockIdx.z;
    int t = threadIdx.x;
    for (int e = t; e < 4800; e += 256) sw[e] = w[z*4800 + e];
    int ty0 = (tile>>1)*16, tx0 = (tile&1)*16;
    int iy0 = 2*ty0 - 2, ix0 = 2*tx0 - 2;
    const float* xb = x + bp*12288;
    for (int e = t; e < 3675; e += 256){
        int c = e/1225, rem = e - c*1225, r = rem/35, col = rem - r*35;
        int gy = iy0 + r, gx = ix0 + col;
        float v = 0.f;
        if (gy>=0 && gy<64 && gx>=0 && gx<64) v = xb[c*4096 + gy*64 + gx];
        sin_[(c*35 + r)*37 + col] = v;
    }
    __syncthreads();
    int px4 = t & 63, cog = t >> 6;
    int ly = px4 >> 2, lx0 = (px4 & 3)*4;
    float* ob = g_s1 + bp*131072;
    for (int p = 0; p < 2; p++){
        int col0 = cog*16 + p*8;
        float acc[8][4];
        #pragma unroll
        for (int i = 0; i < 8; i++){
            float bb = b[z*64 + col0 + i];
            #pragma unroll
            for (int j = 0; j < 4; j++) acc[i][j] = bb;
        }
        #pragma unroll 1
        for (int c = 0; c < 3; c++){
            #pragma unroll
            for (int ky = 0; ky < 5; ky++){
                #pragma unroll
                for (int kx = 0; kx < 5; kx++){
                    float xv[4];
                    #pragma unroll
                    for (int j = 0; j < 4; j++)
                        xv[j] = sin_[(c*35 + 2*ly + ky)*37 + 2*lx0 + 2*j + kx];
                    #pragma unroll
                    for (int i = 0; i < 8; i++){
                        float wv = sw[(col0+i)*75 + c*25 + ky*5 + kx];
                        #pragma unroll
                        for (int j = 0; j < 4; j++) acc[i][j] = fmaf(wv, xv[j], acc[i][j]);
                    }
                }
            }
        }
        #pragma unroll
        for (int i = 0; i < 8; i++){
            float4 o = make_float4(acc[i][0], acc[i][1], acc[i][2], acc[i][3]);
            *reinterpret_cast<float4*>(ob + (z*64+col0+i)*1024 + (ty0+ly)*32 + tx0 + lx0) = o;
        }
    }
}

// ---- GDN in-place. grid BP*HW/64, 256 thr ----
__global__ void gdn_kernel(int stage, const float* __restrict__ beta){
    __shared__ float sA[2048];  // 16 c x 128 d
    __shared__ float sB[1088];  // 16 c x 68 px
    int HW = (stage == 1) ? 1024 : 256;
    float* x = (stage == 1) ? g_s1 : g_s2;
    const float* gT = g_gT[stage-1];
    int chunks = HW >> 6;
    int bp = blockIdx.x / chunks;
    int p0 = (blockIdx.x - bp*chunks) * 64;
    int t = threadIdx.x;
    int i = t >> 4, j = t & 15;
    float* xb = x + bp*128*HW;
    float acc[8][4];
    #pragma unroll
    for (int ii = 0; ii < 8; ii++){
        float bb = beta[i*8 + ii];
        #pragma unroll
        for (int jj = 0; jj < 4; jj++) acc[ii][jj] = bb;
    }
    for (int c0 = 0; c0 < 128; c0 += 16){
        __syncthreads();
        for (int e = t; e < 2048; e += 256) sA[e] = gT[c0*128 + e];
        for (int e = t; e < 1024; e += 256){
            int cc = e >> 6, p = e & 63;
            float v = xb[(c0+cc)*HW + p0 + p];
            sB[cc*68 + p] = v*v;
        }
        __syncthreads();
        #pragma unroll
        for (int cc = 0; cc < 16; cc++){
            float4 xv = *reinterpret_cast<const float4*>(sB + cc*68 + j*4);
            float4 ga = *reinterpret_cast<const float4*>(sA + cc*128 + i*8);
            float4 gb = *reinterpret_cast<const float4*>(sA + cc*128 + i*8 + 4);
            float gs[8] = {ga.x,ga.y,ga.z,ga.w,gb.x,gb.y,gb.z,gb.w};
            #pragma unroll
            for (int ii = 0; ii < 8; ii++){
                acc[ii][0] = fmaf(gs[ii], xv.x, acc[ii][0]);
                acc[ii][1] = fmaf(gs[ii], xv.y, acc[ii][1]);
                acc[ii][2] = fmaf(gs[ii], xv.z, acc[ii][2]);
                acc[ii][3] = fmaf(gs[ii], xv.w, acc[ii][3]);
            }
        }
    }
    #pragma unroll
    for (int ii = 0; ii < 8; ii++){
        int d = i*8 + ii;
        float4 xv = *reinterpret_cast<const float4*>(xb + d*HW + p0 + j*4);
        float4 o;
        o.x = xv.x * rsqrtf(acc[ii][0]);
        o.y = xv.y * rsqrtf(acc[ii][1]);
        o.z = xv.z * rsqrtf(acc[ii][2]);
        o.w = xv.w * rsqrtf(acc[ii][3]);
        *reinterpret_cast<float4*>(xb + d*HW + p0 + j*4) = o;
    }
}

// ---- conv2: 128->128, 5x5, s2, p2 (32x32 -> 16x16). grid (64,4,2), 128 thr ----
__global__ void conv2_kernel(const float* __restrict__ w, const float* __restrict__ b){
    __shared__ float sin_[5624];   // 8ci x 19 x 37
    __shared__ float sw[6400];     // 32co x 8ci x 25
    int bp = blockIdx.x, co0 = blockIdx.y*32, ry0 = blockIdx.z*8;
    int t = threadIdx.x;
    int px4 = t & 31, cs = t >> 5;
    int ly = px4 >> 2, lx0 = (px4 & 3)*4;
    float acc[8][4];
    #pragma unroll
    for (int i = 0; i < 8; i++){
        float bb = b[co0 + cs*8 + i];
        #pragma unroll
        for (int j = 0; j < 4; j++) acc[i][j] = bb;
    }
    const float* xb = g_s1 + bp*131072;
    int iy0 = 2*ry0 - 2;
    for (int ci0 = 0; ci0 < 128; ci0 += 8){
        __syncthreads();
        for (int e = t; e < 5320; e += 128){
            int ci = e/665, rem = e - ci*665, r = rem/35, col = rem - r*35;
            int gy = iy0 + r, gx = col - 2;
            float v = 0.f;
            if (gy>=0 && gy<32 && gx>=0 && gx<32) v = xb[(ci0+ci)*1024 + gy*32 + gx];
            sin_[(ci*19 + r)*37 + col] = v;
        }
        for (int e = t; e < 6400; e += 128){
            int i = e/200, rem = e - i*200;
            sw[e] = w[(co0+i)*3200 + ci0*25 + rem];
        }
        __syncthreads();
        #pragma unroll 1
        for (int ci = 0; ci < 8; ci++){
            #pragma unroll
            for (int ky = 0; ky < 5; ky++){
                #pragma unroll
                for (int kx = 0; kx < 5; kx++){
                    float xv[4];
                    #pragma unroll
                    for (int j = 0; j < 4; j++)
                        xv[j] = sin_[(ci*19 + 2*ly + ky)*37 + 2*lx0 + 2*j + kx];
                    #pragma unroll
                    for (int i = 0; i < 8; i++){
                        float wv = sw[(cs*8+i)*200 + ci*25 + ky*5 + kx];
                        #pragma unroll
                        for (int j = 0; j < 4; j++) acc[i][j] = fmaf(wv, xv[j], acc[i][j]);
                    }
                }
            }
        }
    }
    float* ob = g_s2 + bp*32768;
    #pragma unroll
    for (int i = 0; i < 8; i++){
        float4 o = make_float4(acc[i][0], acc[i][1], acc[i][2], acc[i][3]);
        *reinterpret_cast<float4*>(ob + (co0+cs*8+i)*256 + (ry0+ly)*16 + lx0) = o;
    }
}

// ---- conv3: 128->192, 3x3, s1, p1 (16x16). grid (64,6,2), 128 thr ----
__global__ void conv3_kernel(const float* __restrict__ w, const float* __restrict__ b){
    __shared__ float sin_[1680];   // 8ci x 10 x 21
    __shared__ float sw[2304];     // 32co x 8ci x 9
    int bp = blockIdx.x, co0 = blockIdx.y*32, ry0 = blockIdx.z*8;
    int t = threadIdx.x;
    int px4 = t & 31, cs = t >> 5;
    int ly = px4 >> 2, lx0 = (px4 & 3)*4;
    float acc[8][4];
    #pragma unroll
    for (int i = 0; i < 8; i++){
        float bb = b[co0 + cs*8 + i];
        #pragma unroll
        for (int j = 0; j < 4; j++) acc[i][j] = bb;
    }
    const float* xb = g_s2 + bp*32768;
    int iy0 = ry0 - 1;
    for (int ci0 = 0; ci0 < 128; ci0 += 8){
        __syncthreads();
        for (int e = t; e < 1440; e += 128){
            int ci = e/180, rem = e - ci*180, r = rem/18, col = rem - r*18;
            int gy = iy0 + r, gx = col - 1;
            float v = 0.f;
            if (gy>=0 && gy<16 && gx>=0 && gx<16) v = xb[(ci0+ci)*256 + gy*16 + gx];
            sin_[(ci*10 + r)*21 + col] = v;
        }
        for (int e = t; e < 2304; e += 128){
            int i = e/72, rem = e - i*72;
            sw[e] = w[(co0+i)*1152 + ci0*9 + rem];
        }
        __syncthreads();
        #pragma unroll 1
        for (int ci = 0; ci < 8; ci++){
            #pragma unroll
            for (int ky = 0; ky < 3; ky++){
                #pragma unroll
                for (int kx = 0; kx < 3; kx++){
                    float xv[4];
                    #pragma unroll
                    for (int j = 0; j < 4; j++)
                        xv[j] = sin_[(ci*10 + ly + ky)*21 + lx0 + j + kx];
                    #pragma unroll
                    for (int i = 0; i < 8; i++){
                        float wv = sw[(cs*8+i)*72 + ci*9 + ky*3 + kx];
                        #pragma unroll
                        for (int j = 0; j < 4; j++) acc[i][j] = fmaf(wv, xv[j], acc[i][j]);
                    }
                }
            }
        }
    }
    float* ob = g_y3 + bp*49152;
    #pragma unroll
    for (int i = 0; i < 8; i++){
        float4 o = make_float4(acc[i][0], acc[i][1], acc[i][2], acc[i][3]);
        *reinterpret_cast<float4*>(ob + (co0+cs*8+i)*256 + (ry0+ly)*16 + lx0) = o;
    }
}

// ---- kv: LN + k_proj + v_proj. grid 64, 256 thr ----
__global__ void kv_kernel(const float* __restrict__ yg, const float* __restrict__ lnw,
                          const float* __restrict__ lnb, const float* __restrict__ Wk,
                          const float* __restrict__ Wv){
    __shared__ float s_kv[32*193];
    __shared__ float s_w[64*33];
    int bp = blockIdx.x;
    int t = threadIdx.x;
    int w = t >> 5, l = t & 31;
    for (int e = t; e < 6144; e += 256){
        int c = e >> 5, k = e & 31;
        s_kv[k*193 + c] = yg[bp*6144 + c*32 + k];
    }
    __syncthreads();
    {
        float lwv[6], lbv[6];
        #pragma unroll
        for (int i = 0; i < 6; i++){ lwv[i] = lnw[l+32*i]; lbv[i] = lnb[l+32*i]; }
        for (int ki = 0; ki < 4; ki++){
            int k = w*4 + ki;
            float v[6]; float s = 0.f;
            #pragma unroll
            for (int i = 0; i < 6; i++){ v[i] = s_kv[k*193 + l + 32*i]; s += v[i]; }
            #pragma unroll
            for (int o = 16; o > 0; o >>= 1) s += __shfl_xor_sync(0xffffffffu, s, o);
            float mu = s * (1.f/192.f);
            float vs = 0.f;
            #pragma unroll
            for (int i = 0; i < 6; i++){ float d = v[i]-mu; vs += d*d; }
            #pragma unroll
            for (int o = 16; o > 0; o >>= 1) vs += __shfl_xor_sync(0xffffffffu, vs, o);
            float rs = rsqrtf(vs * (1.f/192.f) + LN_EPS);
            #pragma unroll
            for (int i = 0; i < 6; i++)
                s_kv[k*193 + l + 32*i] = (v[i]-mu)*rs*lwv[i] + lbv[i];
        }
    }
    int kq = t & 7, rp = t >> 3;
    for (int r0 = 0; r0 < 320; r0 += 64){
        float acc[2][4];
        #pragma unroll
        for (int i = 0; i < 2; i++)
            #pragma unroll
            for (int kk = 0; kk < 4; kk++) acc[i][kk] = 0.f;
        for (int c0 = 0; c0 < 192; c0 += 32){
            __syncthreads();
            for (int e = t; e < 2048; e += 256){
                int rr = e >> 5, cc = e & 31;
                int row = r0 + rr;
                s_w[rr*33 + cc] = (row < 128) ? Wk[row*192 + c0 + cc]
                                              : Wv[(row-128)*192 + c0 + cc];
            }
            __syncthreads();
            for (int cc = 0; cc < 32; cc++){
                float wv0 = s_w[(rp*2)*33 + cc], wv1 = s_w[(rp*2+1)*33 + cc];
                #pragma unroll
                for (int kk = 0; kk < 4; kk++){
                    float kvv = s_kv[(kq*4+kk)*193 + c0 + cc];
                    acc[0][kk] = fmaf(wv0, kvv, acc[0][kk]);
                    acc[1][kk] = fmaf(wv1, kvv, acc[1][kk]);
                }
            }
        }
        #pragma unroll
        for (int i = 0; i < 2; i++){
            int row = r0 + rp*2 + i;
            #pragma unroll
            for (int kk = 0; kk < 4; kk++){
                int k = kq*4 + kk;
                if (row < 128) g_kp[bp*4096 + k*128 + row] = acc[i][kk];
                else           g_vp[bp*6144 + k*192 + (row-128)] = acc[i][kk];
            }
        }
    }
}

// ---- attention: grid 512 (bp*8 + qchunk), 256 thr, 95872 B dyn smem ----
__global__ void attn_kernel(const float* __restrict__ lnqw, const float* __restrict__ lnqb,
                            const float* __restrict__ Wq, const float* __restrict__ vw,
                            const float* __restrict__ out_w, const float* __restrict__ out_b,
                            const float* __restrict__ lnow, const float* __restrict__ lnob,
                            float* __restrict__ out){
    extern __shared__ float sm[];
    float* s_qn  = sm;            // 32*193
    float* s_w   = sm + 6176;     // 192*33 (overlaid by vp)
    float* s_kp  = sm + 12512;    // 32*132
    float* s_e   = sm + 16736;    // 32*33
    float* s_ctx = sm + 17792;    // 32*193
    int bp = blockIdx.x >> 3;
    int q0 = (blockIdx.x & 7) << 5;
    int t = threadIdx.x;
    int w = t >> 5, l = t & 31;
    const float* y3 = g_y3 + bp*49152;
    for (int e = t; e < 6144; e += 256){
        int m = e >> 5, q = e & 31;
        s_qn[q*193 + m] = y3[m*256 + q0 + q];
    }
    for (int e = t; e < 4096; e += 256){
        int k = e >> 7;
        s_kp[k*132 + (e & 127)] = g_kp[bp*4096 + e];
    }
    __syncthreads();
    // LN on q rows (warp w owns q = 4w..4w+3)
    {
        float lwv[6], lbv[6];
        #pragma unroll
        for (int i = 0; i < 6; i++){ lwv[i] = lnqw[l+32*i]; lbv[i] = lnqb[l+32*i]; }
        for (int qi = 0; qi < 4; qi++){
            int q = w*4 + qi;
            float v[6]; float s = 0.f;
            #pragma unroll
            for (int i = 0; i < 6; i++){ v[i] = s_qn[q*193 + l + 32*i]; s += v[i]; }
            #pragma unroll
            for (int o = 16; o > 0; o >>= 1) s += __shfl_xor_sync(0xffffffffu, s, o);
            float mu = s * (1.f/192.f);
            float vs = 0.f;
            #pragma unroll
            for (int i = 0; i < 6; i++){ float d = v[i]-mu; vs += d*d; }
            #pragma unroll
            for (int o = 16; o > 0; o >>= 1) vs += __shfl_xor_sync(0xffffffffu, vs, o);
            float rs = rsqrtf(vs * (1.f/192.f) + LN_EPS);
            #pragma unroll
            for (int i = 0; i < 6; i++)
                s_qn[q*193 + l + 32*i] = (v[i]-mu)*rs*lwv[i] + lbv[i];
        }
    }
    // q_proj into regs: qp[qi][j], d = l + 32j
    float qp[4][4];
    #pragma unroll
    for (int a = 0; a < 4; a++)
        #pragma unroll
        for (int b2 = 0; b2 < 4; b2++) qp[a][b2] = 0.f;
    for (int c0 = 0; c0 < 192; c0 += 32){
        __syncthreads();
        for (int e = t; e < 4096; e += 256){
            int d = e >> 5, cc = e & 31;
            s_w[d*33 + cc] = Wq[d*192 + c0 + cc];
        }
        __syncthreads();
        for (int cc = 0; cc < 32; cc++){
            float wv[4], qv[4];
            #pragma unroll
            for (int j = 0; j < 4; j++) wv[j] = s_w[(l+32*j)*33 + cc];
            #pragma unroll
            for (int qi = 0; qi < 4; qi++) qv[qi] = s_qn[(w*4+qi)*193 + c0 + cc];
            #pragma unroll
            for (int qi = 0; qi < 4; qi++)
                #pragma unroll
                for (int j = 0; j < 4; j++) qp[qi][j] = fmaf(qv[qi], wv[j], qp[qi][j]);
        }
    }
    __syncthreads();
    float* s_vp = s_w;   // overlay
    for (int e = t; e < 6144; e += 256){
        int k = e / 192, m = e - k*192;
        s_vp[k*193 + m] = g_vp[bp*6144 + e];
    }
    // energy
    float vv[4];
    #pragma unroll
    for (int j = 0; j < 4; j++) vv[j] = vw[l + 32*j];
    for (int k = 0; k < 32; k++){
        float kp4[4];
        #pragma unroll
        for (int j = 0; j < 4; j++) kp4[j] = s_kp[k*132 + l + 32*j];
        #pragma unroll
        for (int qi = 0; qi < 4; qi++){
            float s = 0.f;
            #pragma unroll
            for (int j = 0; j < 4; j++)
                s = fmaf(tanh_fast(qp[qi][j] + kp4[j]), vv[j], s);
            #pragma unroll
            for (int o = 16; o > 0; o >>= 1) s += __shfl_xor_sync(0xffffffffu, s, o);
            if (l == 0) s_e[(w*4+qi)*33 + k] = s;
        }
    }
    __syncwarp();
    // softmax (own rows)
    for (int qi = 0; qi < 4; qi++){
        int q = w*4 + qi;
        float ev = s_e[q*33 + l];
        float mx = ev;
        #pragma unroll
        for (int o = 16; o > 0; o >>= 1) mx = fmaxf(mx, __shfl_xor_sync(0xffffffffu, mx, o));
        float p = __expf(ev - mx);
        float s = p;
        #pragma unroll
        for (int o = 16; o > 0; o >>= 1) s += __shfl_xor_sync(0xffffffffu, s, o);
        s_e[q*33 + l] = p / s;
    }
    __syncthreads();
    // context
    {
        int qr = t >> 3, mg = t & 7;
        float acc[24];
        #pragma unroll
        for (int i = 0; i < 24; i++) acc[i] = 0.f;
        for (int k = 0; k < 32; k++){
            float a = s_e[qr*33 + k];
            #pragma unroll
            for (int i = 0; i < 24; i++)
                acc[i] = fmaf(a, s_vp[k*193 + mg + 8*i], acc[i]);
        }
        #pragma unroll
        for (int i = 0; i < 24; i++) s_ctx[qr*193 + mg + 8*i] = acc[i];
    }
    __syncthreads();
    // out-proj + residual + LN
    {
        int qh = t >> 4, ng = t & 15;
        float acc0[12], acc1[12];
        #pragma unroll
        for (int i = 0; i < 12; i++){ acc0[i] = 0.f; acc1[i] = 0.f; }
        for (int m0 = 0; m0 < 192; m0 += 32){
            __syncthreads();
            for (int e = t; e < 6144; e += 256){
                int n = e >> 5, mm = e & 31;
                s_w[n*33 + mm] = out_w[n*192 + m0 + mm];
            }
            __syncthreads();
            for (int mm = 0; mm < 32; mm++){
                float c0v = s_ctx[(2*qh)*193 + m0 + mm];
                float c1v = s_ctx[(2*qh+1)*193 + m0 + mm];
                #pragma unroll
                for (int i = 0; i < 12; i++){
                    float wv = s_w[(ng+16*i)*33 + mm];
                    acc0[i] = fmaf(c0v, wv, acc0[i]);
                    acc1[i] = fmaf(c1v, wv, acc1[i]);
                }
            }
        }
        float val0[12], val1[12];
        float s0 = 0.f, s1 = 0.f;
        #pragma unroll
        for (int i = 0; i < 12; i++){
            int n = ng + 16*i;
            val0[i] = acc0[i] + out_b[n] + s_qn[(2*qh)*193 + n];
            val1[i] = acc1[i] + out_b[n] + s_qn[(2*qh+1)*193 + n];
            s0 += val0[i]; s1 += val1[i];
        }
        #pragma unroll
        for (int o = 8; o > 0; o >>= 1){
            s0 += __shfl_xor_sync(0xffffffffu, s0, o);
            s1 += __shfl_xor_sync(0xffffffffu, s1, o);
        }
        float mu0 = s0*(1.f/192.f), mu1 = s1*(1.f/192.f);
        float vs0 = 0.f, vs1 = 0.f;
        #pragma unroll
        for (int i = 0; i < 12; i++){
            float d0 = val0[i]-mu0, d1 = val1[i]-mu1;
            vs0 += d0*d0; vs1 += d1*d1;
        }
        #pragma unroll
        for (int o = 8; o > 0; o >>= 1){
            vs0 += __shfl_xor_sync(0xffffffffu, vs0, o);
            vs1 += __shfl_xor_sync(0xffffffffu, vs1, o);
        }
        float r0 = rsqrtf(vs0*(1.f/192.f) + LN_EPS);
        float r1 = rsqrtf(vs1*(1.f/192.f) + LN_EPS);
        __syncthreads();
        #pragma unroll
        for (int i = 0; i < 12; i++){
            int n = ng + 16*i;
            s_ctx[(2*qh)*193 + n]   = (val0[i]-mu0)*r0*lnow[n] + lnob[n];
            s_ctx[(2*qh+1)*193 + n] = (val1[i]-mu1)*r1*lnow[n] + lnob[n];
        }
    }
    __syncthreads();
    for (int e = t; e < 6144; e += 256){
        int n = e >> 5, q = e & 31;
        out[bp*49152 + n*256 + q0 + q] = s_ctx[q*193 + n];
    }
}

extern "C" void kernel_launch(void* const* d_in, const int* in_sizes, int n_in,
                              void* d_out, int out_size){
    const float* x_p    = (const float*)d_in[0];
    const float* y_g    = (const float*)d_in[1];
    const float* conv1w = (const float*)d_in[2];
    const float* conv1b = (const float*)d_in[3];
    const float* gamma1 = (const float*)d_in[4];
    const float* beta1  = (const float*)d_in[5];
    const float* conv2w = (const float*)d_in[6];
    const float* conv2b = (const float*)d_in[7];
    const float* gamma2 = (const float*)d_in[8];
    const float* beta2  = (const float*)d_in[9];
    const float* conv3w = (const float*)d_in[10];
    const float* conv3b = (const float*)d_in[11];
    const float* lnqw   = (const float*)d_in[12];
    const float* lnqb   = (const float*)d_in[13];
    const float* lnkw   = (const float*)d_in[14];
    const float* lnkb   = (const float*)d_in[15];
    const float* lnow   = (const float*)d_in[16];
    const float* lnob   = (const float*)d_in[17];
    const float* Wq     = (const float*)d_in[18];
    const float* Wk     = (const float*)d_in[19];
    const float* vw     = (const float*)d_in[20];
    const float* Wv     = (const float*)d_in[21];
    const float* outw   = (const float*)d_in[22];
    const float* outb   = (const float*)d_in[23];
    float* out = (float*)d_out;

    cudaFuncSetAttribute(attn_kernel, cudaFuncAttributeMaxDynamicSharedMemorySize, 98304);

    prep_kernel<<<128, 256>>>(gamma1, gamma2);
    conv1_kernel<<<dim3(64,4,2), 256>>>(x_p, conv1w, conv1b);
    gdn_kernel<<<1024, 256>>>(1, beta1);
    conv2_kernel<<<dim3(64,4,2), 128>>>(conv2w, conv2b);
    gdn_kernel<<<256, 256>>>(2, beta2);
    conv3_kernel<<<dim3(64,6,2), 128>>>(conv3w, conv3b);
    kv_kernel<<<64, 256>>>(y_g, lnkw, lnkb, Wk, Wv);
    attn_kernel<<<512, 256, 95872>>>(lnqw, lnqb, Wq, vw, outw, outb, lnow, lnob, out);
}

// round 3
// speedup vs baseline: 1.0633x; 1.0633x over previous
#include <cuda_runtime.h>

#define LN_EPS 1e-5f
typedef unsigned long long ull;

// ---- scratch ----
__device__ float g_s1[64*128*1024];
__device__ float g_s2[64*128*256];
__device__ float g_y3[64*192*256];
__device__ float g_kp[64*32*128];
__device__ float g_vp[64*32*192];
__device__ float g_gT[2][16384];

__device__ __forceinline__ float tanh_fast(float x){
    float y; asm("tanh.approx.f32 %0, %1;" : "=f"(y) : "f"(x)); return y;
}
__device__ __forceinline__ ull pk2(float lo, float hi){
    ull r; asm("mov.b64 %0, {%1, %2};" : "=l"(r) : "f"(lo), "f"(hi)); return r;
}
__device__ __forceinline__ ull pkdup(float v){ return pk2(v, v); }
__device__ __forceinline__ void upk2(ull p, float& lo, float& hi){
    asm("mov.b64 {%0, %1}, %2;" : "=f"(lo), "=f"(hi) : "l"(p));
}
__device__ __forceinline__ ull ffma2(ull a, ull b, ull c){
    ull d; asm("fma.rn.f32x2 %0, %1, %2, %3;" : "=l"(d) : "l"(a), "l"(b), "l"(c)); return d;
}

// ---- prep: transpose gammas ----
__global__ void prep_kernel(const float* __restrict__ g1, const float* __restrict__ g2){
    int bwhich = blockIdx.x >> 6;
    int e = ((blockIdx.x & 63) << 8) + threadIdx.x;
    const float* g = bwhich ? g2 : g1;
    int d = e >> 7, c = e & 127;
    g_gT[bwhich][c*128 + d] = g[e];
}

// ---- conv1: 3->128, 5x5, s2, p2 (64x64 -> 32x32). grid (64,4,2), 256 thr ----
__global__ void conv1_kernel(const float* __restrict__ x, const float* __restrict__ w,
                             const float* __restrict__ b){
    __shared__ float sw[4800];
    __shared__ float sin_[3885];
    int bp = blockIdx.x, tile = blockIdx.y, z = blockIdx.z;
    int t = threadIdx.x;
    for (int e = t; e < 4800; e += 256) sw[e] = w[z*4800 + e];
    int ty0 = (tile>>1)*16, tx0 = (tile&1)*16;
    int iy0 = 2*ty0 - 2, ix0 = 2*tx0 - 2;
    const float* xb = x + bp*12288;
    for (int e = t; e < 3675; e += 256){
        int c = e/1225, rem = e - c*1225, r = rem/35, col = rem - r*35;
        int gy = iy0 + r, gx = ix0 + col;
        float v = 0.f;
        if (gy>=0 && gy<64 && gx>=0 && gx<64) v = xb[c*4096 + gy*64 + gx];
        sin_[(c*35 + r)*37 + col] = v;
    }
    __syncthreads();
    int px4 = t & 63, cog = t >> 6;
    int ly = px4 >> 2, lx0 = (px4 & 3)*4;
    float* ob = g_s1 + bp*131072;
    for (int p = 0; p < 2; p++){
        int col0 = cog*16 + p*8;
        float acc[8][4];
        #pragma unroll
        for (int i = 0; i < 8; i++){
            float bb = b[z*64 + col0 + i];
            #pragma unroll
            for (int j = 0; j < 4; j++) acc[i][j] = bb;
        }
        #pragma unroll 1
        for (int c = 0; c < 3; c++){
            #pragma unroll
            for (int ky = 0; ky < 5; ky++){
                #pragma unroll
                for (int kx = 0; kx < 5; kx++){
                    float xv[4];
                    #pragma unroll
                    for (int j = 0; j < 4; j++)
                        xv[j] = sin_[(c*35 + 2*ly + ky)*37 + 2*lx0 + 2*j + kx];
                    #pragma unroll
                    for (int i = 0; i < 8; i++){
                        float wv = sw[(col0+i)*75 + c*25 + ky*5 + kx];
                        #pragma unroll
                        for (int j = 0; j < 4; j++) acc[i][j] = fmaf(wv, xv[j], acc[i][j]);
                    }
                }
            }
        }
        #pragma unroll
        for (int i = 0; i < 8; i++){
            float4 o = make_float4(acc[i][0], acc[i][1], acc[i][2], acc[i][3]);
            *reinterpret_cast<float4*>(ob + (z*64+col0+i)*1024 + (ty0+ly)*32 + tx0 + lx0) = o;
        }
    }
}

// ---- GDN in-place (f32x2). grid BP*HW/64, 256 thr ----
__global__ void gdn_kernel(int stage, const float* __restrict__ beta){
    __shared__ float sA[2048];  // 16 c x 128 d
    __shared__ float sB[1088];  // 16 c x 68 px
    int HW = (stage == 1) ? 1024 : 256;
    float* x = (stage == 1) ? g_s1 : g_s2;
    const float* gT = g_gT[stage-1];
    int chunks = HW >> 6;
    int bp = blockIdx.x / chunks;
    int p0 = (blockIdx.x - bp*chunks) * 64;
    int t = threadIdx.x;
    int i = t >> 4, j = t & 15;
    float* xb = x + bp*128*HW;
    ull acc[8][2];
    #pragma unroll
    for (int ii = 0; ii < 8; ii++){
        float bb = beta[i*8 + ii];
        acc[ii][0] = pkdup(bb); acc[ii][1] = pkdup(bb);
    }
    for (int c0 = 0; c0 < 128; c0 += 16){
        __syncthreads();
        for (int e = t; e < 2048; e += 256) sA[e] = gT[c0*128 + e];
        for (int e = t; e < 1024; e += 256){
            int cc = e >> 6, p = e & 63;
            float v = xb[(c0+cc)*HW + p0 + p];
            sB[cc*68 + p] = v*v;
        }
        __syncthreads();
        #pragma unroll
        for (int cc = 0; cc < 16; cc++){
            const ull* xp = reinterpret_cast<const ull*>(sB + cc*68 + j*4);
            ull x0 = xp[0], x1 = xp[1];
            float4 ga = *reinterpret_cast<const float4*>(sA + cc*128 + i*8);
            float4 gb = *reinterpret_cast<const float4*>(sA + cc*128 + i*8 + 4);
            float gs[8] = {ga.x,ga.y,ga.z,ga.w,gb.x,gb.y,gb.z,gb.w};
            #pragma unroll
            for (int ii = 0; ii < 8; ii++){
                ull wp = pkdup(gs[ii]);
                acc[ii][0] = ffma2(x0, wp, acc[ii][0]);
                acc[ii][1] = ffma2(x1, wp, acc[ii][1]);
            }
        }
    }
    #pragma unroll
    for (int ii = 0; ii < 8; ii++){
        int d = i*8 + ii;
        float a0,a1,a2,a3;
        upk2(acc[ii][0], a0, a1);
        upk2(acc[ii][1], a2, a3);
        float4 xv = *reinterpret_cast<const float4*>(xb + d*HW + p0 + j*4);
        float4 o;
        o.x = xv.x * rsqrtf(a0);
        o.y = xv.y * rsqrtf(a1);
        o.z = xv.z * rsqrtf(a2);
        o.w = xv.w * rsqrtf(a3);
        *reinterpret_cast<float4*>(xb + d*HW + p0 + j*4) = o;
    }
}

// ---- conv2 (f32x2): 128->128, 5x5, s2, p2. grid (64,2,2), 128 thr, dyn smem ----
__global__ void __launch_bounds__(128, 3) conv2_kernel(const float* __restrict__ w,
                                                       const float* __restrict__ b){
    extern __shared__ float sm2[];
    float* sin_ = sm2;          // 8ci x 19 x 37 = 5624
    float* sw   = sm2 + 5624;   // 64co x 200 = 12800
    int bp = blockIdx.x, co0 = blockIdx.y*64, ry0 = blockIdx.z*8;
    int t = threadIdx.x;
    int pxg = t & 15, cs = t >> 4;          // cs 0..7
    int ly = pxg >> 1, lx0 = (pxg & 1)*8;   // ly 0..7, lx0 0/8
    ull acc[8][4];
    #pragma unroll
    for (int i = 0; i < 8; i++){
        float bb = b[co0 + cs*8 + i];
        #pragma unroll
        for (int jj = 0; jj < 4; jj++) acc[i][jj] = pkdup(bb);
    }
    const float* xb = g_s1 + bp*131072;
    int iy0 = 2*ry0 - 2;
    for (int ci0 = 0; ci0 < 128; ci0 += 8){
        __syncthreads();
        for (int e = t; e < 5320; e += 128){
            int ci = e/665, rem = e - ci*665, r = rem/35, col = rem - r*35;
            int gy = iy0 + r, gx = col - 2;
            float v = 0.f;
            if (gy>=0 && gy<32 && gx>=0 && gx<32) v = xb[(ci0+ci)*1024 + gy*32 + gx];
            sin_[(ci*19 + r)*37 + col] = v;
        }
        for (int e = t; e < 12800; e += 128){
            int i = e/200, rem = e - i*200;
            sw[e] = w[(co0+i)*3200 + ci0*25 + rem];
        }
        __syncthreads();
        #pragma unroll 1
        for (int ci = 0; ci < 8; ci++){
            #pragma unroll 1
            for (int ky = 0; ky < 5; ky++){
                const float* srow = sin_ + (ci*19 + 2*ly + ky)*37 + 2*lx0;
                const float* wrow = sw + cs*8*200 + ci*25 + ky*5;
                #pragma unroll
                for (int kx = 0; kx < 5; kx++){
                    ull xp[4];
                    #pragma unroll
                    for (int jj = 0; jj < 4; jj++)
                        xp[jj] = pk2(srow[4*jj + kx], srow[4*jj + kx + 2]);
                    #pragma unroll
                    for (int i = 0; i < 8; i++){
                        ull wp = pkdup(wrow[i*200 + kx]);
                        #pragma unroll
                        for (int jj = 0; jj < 4; jj++)
                            acc[i][jj] = ffma2(xp[jj], wp, acc[i][jj]);
                    }
                }
            }
        }
    }
    float* ob = g_s2 + bp*32768;
    #pragma unroll
    for (int i = 0; i < 8; i++){
        float* orow = ob + (co0 + cs*8 + i)*256 + (ry0+ly)*16 + lx0;
        #pragma unroll
        for (int jj = 0; jj < 4; jj++)
            *reinterpret_cast<ull*>(orow + 2*jj) = acc[i][jj];
    }
}

// ---- conv3 (f32x2): 128->192, 3x3, s1, p1. grid (64,3,2), 128 thr ----
__global__ void __launch_bounds__(128) conv3_kernel(const float* __restrict__ w,
                                                    const float* __restrict__ b){
    __shared__ float sin_[2100];   // 8ci x 10 x 21
    __shared__ float sw[4608];     // 64co x 8ci x 9
    int bp = blockIdx.x, co0 = blockIdx.y*64, ry0 = blockIdx.z*8;
    int t = threadIdx.x;
    int pxg = t & 15, cs = t >> 4;
    int ly = pxg >> 1, lx0 = (pxg & 1)*8;
    ull acc[8][4];
    #pragma unroll
    for (int i = 0; i < 8; i++){
        float bb = b[co0 + cs*8 + i];
        #pragma unroll
        for (int jj = 0; jj < 4; jj++) acc[i][jj] = pkdup(bb);
    }
    const float* xb = g_s2 + bp*32768;
    int iy0 = ry0 - 1;
    for (int ci0 = 0; ci0 < 128; ci0 += 8){
        __syncthreads();
        for (int e = t; e < 1440; e += 128){
            int ci = e/180, rem = e - ci*180, r = rem/18, col = rem - r*18;
            int gy = iy0 + r, gx = col - 1;
            float v = 0.f;
            if (gy>=0 && gy<16 && gx>=0 && gx<16) v = xb[(ci0+ci)*256 + gy*16 + gx];
            sin_[(ci*10 + r)*21 + col] = v;
        }
        for (int e = t; e < 4608; e += 128){
            int i = e/72, rem = e - i*72;
            sw[e] = w[(co0+i)*1152 + ci0*9 + rem];
        }
        __syncthreads();
        #pragma unroll 1
        for (int ci = 0; ci < 8; ci++){
            #pragma unroll 1
            for (int ky = 0; ky < 3; ky++){
                const float* srow = sin_ + (ci*10 + ly + ky)*21 + lx0;
                const float* wrow = sw + cs*8*72 + ci*9 + ky*3;
                #pragma unroll
                for (int kx = 0; kx < 3; kx++){
                    ull xp[4];
                    #pragma unroll
                    for (int jj = 0; jj < 4; jj++)
                        xp[jj] = pk2(srow[2*jj + kx], srow[2*jj + kx + 1]);
                    #pragma unroll
                    for (int i = 0; i < 8; i++){
                        ull wp = pkdup(wrow[i*72 + kx]);
                        #pragma unroll
                        for (int jj = 0; jj < 4; jj++)
                            acc[i][jj] = ffma2(xp[jj], wp, acc[i][jj]);
                    }
                }
            }
        }
    }
    float* ob = g_y3 + bp*49152;
    #pragma unroll
    for (int i = 0; i < 8; i++){
        float* orow = ob + (co0 + cs*8 + i)*256 + (ry0+ly)*16 + lx0;
        #pragma unroll
        for (int jj = 0; jj < 4; jj++)
            *reinterpret_cast<ull*>(orow + 2*jj) = acc[i][jj];
    }
}

// ---- kv: LN + k_proj + v_proj. grid 64, 256 thr ----
__global__ void kv_kernel(const float* __restrict__ yg, const float* __restrict__ lnw,
                          const float* __restrict__ lnb, const float* __restrict__ Wk,
                          const float* __restrict__ Wv){
    __shared__ float s_kv[32*193];
    __shared__ float s_w[64*33];
    int bp = blockIdx.x;
    int t = threadIdx.x;
    int w = t >> 5, l = t & 31;
    for (int e = t; e < 6144; e += 256){
        int c = e >> 5, k = e & 31;
        s_kv[k*193 + c] = yg[bp*6144 + c*32 + k];
    }
    __syncthreads();
    {
        float lwv[6], lbv[6];
        #pragma unroll
        for (int i = 0; i < 6; i++){ lwv[i] = lnw[l+32*i]; lbv[i] = lnb[l+32*i]; }
        for (int ki = 0; ki < 4; ki++){
            int k = w*4 + ki;
            float v[6]; float s = 0.f;
            #pragma unroll
            for (int i = 0; i < 6; i++){ v[i] = s_kv[k*193 + l + 32*i]; s += v[i]; }
            #pragma unroll
            for (int o = 16; o > 0; o >>= 1) s += __shfl_xor_sync(0xffffffffu, s, o);
            float mu = s * (1.f/192.f);
            float vs = 0.f;
            #pragma unroll
            for (int i = 0; i < 6; i++){ float d = v[i]-mu; vs += d*d; }
            #pragma unroll
            for (int o = 16; o > 0; o >>= 1) vs += __shfl_xor_sync(0xffffffffu, vs, o);
            float rs = rsqrtf(vs * (1.f/192.f) + LN_EPS);
            #pragma unroll
            for (int i = 0; i < 6; i++)
                s_kv[k*193 + l + 32*i] = (v[i]-mu)*rs*lwv[i] + lbv[i];
        }
    }
    int kq = t & 7, rp = t >> 3;
    for (int r0 = 0; r0 < 320; r0 += 64){
        float acc[2][4];
        #pragma unroll
        for (int i = 0; i < 2; i++)
            #pragma unroll
            for (int kk = 0; kk < 4; kk++) acc[i][kk] = 0.f;
        for (int c0 = 0; c0 < 192; c0 += 32){
            __syncthreads();
            for (int e = t; e < 2048; e += 256){
                int rr = e >> 5, cc = e & 31;
                int row = r0 + rr;
                s_w[rr*33 + cc] = (row < 128) ? Wk[row*192 + c0 + cc]
                                              : Wv[(row-128)*192 + c0 + cc];
            }
            __syncthreads();
            for (int cc = 0; cc < 32; cc++){
                float wv0 = s_w[(rp*2)*33 + cc], wv1 = s_w[(rp*2+1)*33 + cc];
                #pragma unroll
                for (int kk = 0; kk < 4; kk++){
                    float kvv = s_kv[(kq*4+kk)*193 + c0 + cc];
                    acc[0][kk] = fmaf(wv0, kvv, acc[0][kk]);
                    acc[1][kk] = fmaf(wv1, kvv, acc[1][kk]);
                }
            }
        }
        #pragma unroll
        for (int i = 0; i < 2; i++){
            int row = r0 + rp*2 + i;
            #pragma unroll
            for (int kk = 0; kk < 4; kk++){
                int k = kq*4 + kk;
                if (row < 128) g_kp[bp*4096 + k*128 + row] = acc[i][kk];
                else           g_vp[bp*6144 + k*192 + (row-128)] = acc[i][kk];
            }
        }
    }
}

// ---- attention: grid 512, 256 thr, 95872 B dyn smem ----
__global__ void attn_kernel(const float* __restrict__ lnqw, const float* __restrict__ lnqb,
                            const float* __restrict__ Wq, const float* __restrict__ vw,
                            const float* __restrict__ out_w, const float* __restrict__ out_b,
                            const float* __restrict__ lnow, const float* __restrict__ lnob,
                            float* __restrict__ out){
    extern __shared__ float sm[];
    float* s_qn  = sm;            // 32*193
    float* s_w   = sm + 6176;     // 192*33 (overlaid by vp)
    float* s_kp  = sm + 12512;    // 32*132
    float* s_e   = sm + 16736;    // 32*33
    float* s_ctx = sm + 17792;    // 32*193
    int bp = blockIdx.x >> 3;
    int q0 = (blockIdx.x & 7) << 5;
    int t = threadIdx.x;
    int w = t >> 5, l = t & 31;
    const float* y3 = g_y3 + bp*49152;
    for (int e = t; e < 6144; e += 256){
        int m = e >> 5, q = e & 31;
        s_qn[q*193 + m] = y3[m*256 + q0 + q];
    }
    for (int e = t; e < 4096; e += 256){
        int k = e >> 7;
        s_kp[k*132 + (e & 127)] = g_kp[bp*4096 + e];
    }
    __syncthreads();
    {
        float lwv[6], lbv[6];
        #pragma unroll
        for (int i = 0; i < 6; i++){ lwv[i] = lnqw[l+32*i]; lbv[i] = lnqb[l+32*i]; }
        for (int qi = 0; qi < 4; qi++){
            int q = w*4 + qi;
            float v[6]; float s = 0.f;
            #pragma unroll
            for (int i = 0; i < 6; i++){ v[i] = s_qn[q*193 + l + 32*i]; s += v[i]; }
            #pragma unroll
            for (int o = 16; o > 0; o >>= 1) s += __shfl_xor_sync(0xffffffffu, s, o);
            float mu = s * (1.f/192.f);
            float vs = 0.f;
            #pragma unroll
            for (int i = 0; i < 6; i++){ float d = v[i]-mu; vs += d*d; }
            #pragma unroll
            for (int o = 16; o > 0; o >>= 1) vs += __shfl_xor_sync(0xffffffffu, vs, o);
            float rs = rsqrtf(vs * (1.f/192.f) + LN_EPS);
            #pragma unroll
            for (int i = 0; i < 6; i++)
                s_qn[q*193 + l + 32*i] = (v[i]-mu)*rs*lwv[i] + lbv[i];
        }
    }
    float qp[4][4];
    #pragma unroll
    for (int a = 0; a < 4; a++)
        #pragma unroll
        for (int b2 = 0; b2 < 4; b2++) qp[a][b2] = 0.f;
    for (int c0 = 0; c0 < 192; c0 += 32){
        __syncthreads();
        for (int e = t; e < 4096; e += 256){
            int d = e >> 5, cc = e & 31;
            s_w[d*33 + cc] = Wq[d*192 + c0 + cc];
        }
        __syncthreads();
        for (int cc = 0; cc < 32; cc++){
            float wv[4], qv[4];
            #pragma unroll
            for (int j = 0; j < 4; j++) wv[j] = s_w[(l+32*j)*33 + cc];
            #pragma unroll
            for (int qi = 0; qi < 4; qi++) qv[qi] = s_qn[(w*4+qi)*193 + c0 + cc];
            #pragma unroll
            for (int qi = 0; qi < 4; qi++)
                #pragma unroll
                for (int j = 0; j < 4; j++) qp[qi][j] = fmaf(qv[qi], wv[j], qp[qi][j]);
        }
    }
    __syncthreads();
    float* s_vp = s_w;
    for (int e = t; e < 6144; e += 256){
        int k = e / 192, m = e - k*192;
        s_vp[k*193 + m] = g_vp[bp*6144 + e];
    }
    float vv[4];
    #pragma unroll
    for (int j = 0; j < 4; j++) vv[j] = vw[l + 32*j];
    for (int k = 0; k < 32; k++){
        float kp4[4];
        #pragma unroll
        for (int j = 0; j < 4; j++) kp4[j] = s_kp[k*132 + l + 32*j];
        #pragma unroll
        for (int qi = 0; qi < 4; qi++){
            float s = 0.f;
            #pragma unroll
            for (int j = 0; j < 4; j++)
                s = fmaf(tanh_fast(qp[qi][j] + kp4[j]), vv[j], s);
            #pragma unroll
            for (int o = 16; o > 0; o >>= 1) s += __shfl_xor_sync(0xffffffffu, s, o);
            if (l == 0) s_e[(w*4+qi)*33 + k] = s;
        }
    }
    __syncwarp();
    for (int qi = 0; qi < 4; qi++){
        int q = w*4 + qi;
        float ev = s_e[q*33 + l];
        float mx = ev;
        #pragma unroll
        for (int o = 16; o > 0; o >>= 1) mx = fmaxf(mx, __shfl_xor_sync(0xffffffffu, mx, o));
        float p = __expf(ev - mx);
        float s = p;
        #pragma unroll
        for (int o = 16; o > 0; o >>= 1) s += __shfl_xor_sync(0xffffffffu, s, o);
        s_e[q*33 + l] = p / s;
    }
    __syncthreads();
    {
        int qr = t >> 3, mg = t & 7;
        float acc[24];
        #pragma unroll
        for (int i = 0; i < 24; i++) acc[i] = 0.f;
        for (int k = 0; k < 32; k++){
            float a = s_e[qr*33 + k];
            #pragma unroll
            for (int i = 0; i < 24; i++)
                acc[i] = fmaf(a, s_vp[k*193 + mg + 8*i], acc[i]);
        }
        #pragma unroll
        for (int i = 0; i < 24; i++) s_ctx[qr*193 + mg + 8*i] = acc[i];
    }
    __syncthreads();
    {
        int qh = t >> 4, ng = t & 15;
        float acc0[12], acc1[12];
        #pragma unroll
        for (int i = 0; i < 12; i++){ acc0[i] = 0.f; acc1[i] = 0.f; }
        for (int m0 = 0; m0 < 192; m0 += 32){
            __syncthreads();
            for (int e = t; e < 6144; e += 256){
                int n = e >> 5, mm = e & 31;
                s_w[n*33 + mm] = out_w[n*192 + m0 + mm];
            }
            __syncthreads();
            for (int mm = 0; mm < 32; mm++){
                float c0v = s_ctx[(2*qh)*193 + m0 + mm];
                float c1v = s_ctx[(2*qh+1)*193 + m0 + mm];
                #pragma unroll
                for (int i = 0; i < 12; i++){
                    float wv = s_w[(ng+16*i)*33 + mm];
                    acc0[i] = fmaf(c0v, wv, acc0[i]);
                    acc1[i] = fmaf(c1v, wv, acc1[i]);
                }
            }
        }
        float val0[12], val1[12];
        float s0 = 0.f, s1 = 0.f;
        #pragma unroll
        for (int i = 0; i < 12; i++){
            int n = ng + 16*i;
            val0[i] = acc0[i] + out_b[n] + s_qn[(2*qh)*193 + n];
            val1[i] = acc1[i] + out_b[n] + s_qn[(2*qh+1)*193 + n];
            s0 += val0[i]; s1 += val1[i];
        }
        #pragma unroll
        for (int o = 8; o > 0; o >>= 1){
            s0 += __shfl_xor_sync(0xffffffffu, s0, o);
            s1 += __shfl_xor_sync(0xffffffffu, s1, o);
        }
        float mu0 = s0*(1.f/192.f), mu1 = s1*(1.f/192.f);
        float vs0 = 0.f, vs1 = 0.f;
        #pragma unroll
        for (int i = 0; i < 12; i++){
            float d0 = val0[i]-mu0, d1 = val1[i]-mu1;
            vs0 += d0*d0; vs1 += d1*d1;
        }
        #pragma unroll
        for (int o = 8; o > 0; o >>= 1){
            vs0 += __shfl_xor_sync(0xffffffffu, vs0, o);
            vs1 += __shfl_xor_sync(0xffffffffu, vs1, o);
        }
        float r0 = rsqrtf(vs0*(1.f/192.f) + LN_EPS);
        float r1 = rsqrtf(vs1*(1.f/192.f) + LN_EPS);
        __syncthreads();
        #pragma unroll
        for (int i = 0; i < 12; i++){
            int n = ng + 16*i;
            s_ctx[(2*qh)*193 + n]   = (val0[i]-mu0)*r0*lnow[n] + lnob[n];
            s_ctx[(2*qh+1)*193 + n] = (val1[i]-mu1)*r1*lnow[n] + lnob[n];
        }
    }
    __syncthreads();
    for (int e = t; e < 6144; e += 256){
        int n = e >> 5, q = e & 31;
        out[bp*49152 + n*256 + q0 + q] = s_ctx[q*193 + n];
    }
}

extern "C" void kernel_launch(void* const* d_in, const int* in_sizes, int n_in,
                              void* d_out, int out_size){
    const float* x_p    = (const float*)d_in[0];
    const float* y_g    = (const float*)d_in[1];
    const float* conv1w = (const float*)d_in[2];
    const float* conv1b = (const float*)d_in[3];
    const float* gamma1 = (const float*)d_in[4];
    const float* beta1  = (const float*)d_in[5];
    const float* conv2w = (const float*)d_in[6];
    const float* conv2b = (const float*)d_in[7];
    const float* gamma2 = (const float*)d_in[8];
    const float* beta2  = (const float*)d_in[9];
    const float* conv3w = (const float*)d_in[10];
    const float* conv3b = (const float*)d_in[11];
    const float* lnqw   = (const float*)d_in[12];
    const float* lnqb   = (const float*)d_in[13];
    const float* lnkw   = (const float*)d_in[14];
    const float* lnkb   = (const float*)d_in[15];
    const float* lnow   = (const float*)d_in[16];
    const float* lnob   = (const float*)d_in[17];
    const float* Wq     = (const float*)d_in[18];
    const float* Wk     = (const float*)d_in[19];
    const float* vw     = (const float*)d_in[20];
    const float* Wv     = (const float*)d_in[21];
    const float* outw   = (const float*)d_in[22];
    const float* outb   = (const float*)d_in[23];
    float* out = (float*)d_out;

    cudaFuncSetAttribute(attn_kernel, cudaFuncAttributeMaxDynamicSharedMemorySize, 98304);
    cudaFuncSetAttribute(conv2_kernel, cudaFuncAttributeMaxDynamicSharedMemorySize, 73696);

    prep_kernel<<<128, 256>>>(gamma1, gamma2);
    conv1_kernel<<<dim3(64,4,2), 256>>>(x_p, conv1w, conv1b);
    gdn_kernel<<<1024, 256>>>(1, beta1);
    conv2_kernel<<<dim3(64,2,2), 128, 73696>>>(conv2w, conv2b);
    gdn_kernel<<<256, 256>>>(2, beta2);
    conv3_kernel<<<dim3(64,3,2), 128>>>(conv3w, conv3b);
    kv_kernel<<<64, 256>>>(y_g, lnkw, lnkb, Wk, Wv);
    attn_kernel<<<512, 256, 95872>>>(lnqw, lnqb, Wq, vw, outw, outb, lnow, lnob, out);
}

// round 4
// speedup vs baseline: 1.0661x; 1.0026x over previous
#include <cuda_runtime.h>

#define LN_EPS 1e-5f
typedef unsigned long long ull;

// ---- scratch ----
__device__ float g_s1[64*128*1024];
__device__ float g_s2[64*128*256];
__device__ float g_y3[64*192*256];
__device__ float g_kp[64*32*128];
__device__ float g_vp[64*32*192];
__device__ float g_gT[2][16384];

__device__ __forceinline__ float tanh_fast(float x){
    float y; asm("tanh.approx.f32 %0, %1;" : "=f"(y) : "f"(x)); return y;
}
__device__ __forceinline__ ull pk2(float lo, float hi){
    ull r; asm("mov.b64 %0, {%1, %2};" : "=l"(r) : "f"(lo), "f"(hi)); return r;
}
__device__ __forceinline__ ull pkdup(float v){ return pk2(v, v); }
__device__ __forceinline__ void upk2(ull p, float& lo, float& hi){
    asm("mov.b64 {%0, %1}, %2;" : "=f"(lo), "=f"(hi) : "l"(p));
}
__device__ __forceinline__ ull ffma2(ull a, ull b, ull c){
    ull d; asm("fma.rn.f32x2 %0, %1, %2, %3;" : "=l"(d) : "l"(a), "l"(b), "l"(c)); return d;
}

// ---- prep: transpose gammas ----
__global__ void prep_kernel(const float* __restrict__ g1, const float* __restrict__ g2){
    int bwhich = blockIdx.x >> 6;
    int e = ((blockIdx.x & 63) << 8) + threadIdx.x;
    const float* g = bwhich ? g2 : g1;
    int d = e >> 7, c = e & 127;
    g_gT[bwhich][c*128 + d] = g[e];
}

// ---- conv1: 3->128, 5x5, s2, p2 (64x64 -> 32x32). grid (64,4,2), 256 thr ----
__global__ void conv1_kernel(const float* __restrict__ x, const float* __restrict__ w,
                             const float* __restrict__ b){
    __shared__ float sw[4800];
    __shared__ float sin_[3885];
    int bp = blockIdx.x, tile = blockIdx.y, z = blockIdx.z;
    int t = threadIdx.x;
    for (int e = t; e < 4800; e += 256) sw[e] = w[z*4800 + e];
    int ty0 = (tile>>1)*16, tx0 = (tile&1)*16;
    int iy0 = 2*ty0 - 2, ix0 = 2*tx0 - 2;
    const float* xb = x + bp*12288;
    for (int e = t; e < 3675; e += 256){
        int c = e/1225, rem = e - c*1225, r = rem/35, col = rem - r*35;
        int gy = iy0 + r, gx = ix0 + col;
        float v = 0.f;
        if (gy>=0 && gy<64 && gx>=0 && gx<64) v = xb[c*4096 + gy*64 + gx];
        sin_[(c*35 + r)*37 + col] = v;
    }
    __syncthreads();
    int px4 = t & 63, cog = t >> 6;
    int ly = px4 >> 2, lx0 = (px4 & 3)*4;
    float* ob = g_s1 + bp*131072;
    for (int p = 0; p < 2; p++){
        int col0 = cog*16 + p*8;
        float acc[8][4];
        #pragma unroll
        for (int i = 0; i < 8; i++){
            float bb = b[z*64 + col0 + i];
            #pragma unroll
            for (int j = 0; j < 4; j++) acc[i][j] = bb;
        }
        #pragma unroll 1
        for (int c = 0; c < 3; c++){
            #pragma unroll
            for (int ky = 0; ky < 5; ky++){
                #pragma unroll
                for (int kx = 0; kx < 5; kx++){
                    float xv[4];
                    #pragma unroll
                    for (int j = 0; j < 4; j++)
                        xv[j] = sin_[(c*35 + 2*ly + ky)*37 + 2*lx0 + 2*j + kx];
                    #pragma unroll
                    for (int i = 0; i < 8; i++){
                        float wv = sw[(col0+i)*75 + c*25 + ky*5 + kx];
                        #pragma unroll
                        for (int j = 0; j < 4; j++) acc[i][j] = fmaf(wv, xv[j], acc[i][j]);
                    }
                }
            }
        }
        #pragma unroll
        for (int i = 0; i < 8; i++){
            float4 o = make_float4(acc[i][0], acc[i][1], acc[i][2], acc[i][3]);
            *reinterpret_cast<float4*>(ob + (z*64+col0+i)*1024 + (ty0+ly)*32 + tx0 + lx0) = o;
        }
    }
}

// ---- GDN in-place (f32x2). grid BP*HW/64, 256 thr ----
__global__ void gdn_kernel(int stage, const float* __restrict__ beta){
    __shared__ float sA[2048];
    __shared__ float sB[1088];
    int HW = (stage == 1) ? 1024 : 256;
    float* x = (stage == 1) ? g_s1 : g_s2;
    const float* gT = g_gT[stage-1];
    int chunks = HW >> 6;
    int bp = blockIdx.x / chunks;
    int p0 = (blockIdx.x - bp*chunks) * 64;
    int t = threadIdx.x;
    int i = t >> 4, j = t & 15;
    float* xb = x + bp*128*HW;
    ull acc[8][2];
    #pragma unroll
    for (int ii = 0; ii < 8; ii++){
        float bb = beta[i*8 + ii];
        acc[ii][0] = pkdup(bb); acc[ii][1] = pkdup(bb);
    }
    for (int c0 = 0; c0 < 128; c0 += 16){
        __syncthreads();
        for (int e = t; e < 2048; e += 256) sA[e] = gT[c0*128 + e];
        for (int e = t; e < 1024; e += 256){
            int cc = e >> 6, p = e & 63;
            float v = xb[(c0+cc)*HW + p0 + p];
            sB[cc*68 + p] = v*v;
        }
        __syncthreads();
        #pragma unroll
        for (int cc = 0; cc < 16; cc++){
            const ull* xp = reinterpret_cast<const ull*>(sB + cc*68 + j*4);
            ull x0 = xp[0], x1 = xp[1];
            float4 ga = *reinterpret_cast<const float4*>(sA + cc*128 + i*8);
            float4 gb = *reinterpret_cast<const float4*>(sA + cc*128 + i*8 + 4);
            float gs[8] = {ga.x,ga.y,ga.z,ga.w,gb.x,gb.y,gb.z,gb.w};
            #pragma unroll
            for (int ii = 0; ii < 8; ii++){
                ull wp = pkdup(gs[ii]);
                acc[ii][0] = ffma2(x0, wp, acc[ii][0]);
                acc[ii][1] = ffma2(x1, wp, acc[ii][1]);
            }
        }
    }
    #pragma unroll
    for (int ii = 0; ii < 8; ii++){
        int d = i*8 + ii;
        float a0,a1,a2,a3;
        upk2(acc[ii][0], a0, a1);
        upk2(acc[ii][1], a2, a3);
        float4 xv = *reinterpret_cast<const float4*>(xb + d*HW + p0 + j*4);
        float4 o;
        o.x = xv.x * rsqrtf(a0);
        o.y = xv.y * rsqrtf(a1);
        o.z = xv.z * rsqrtf(a2);
        o.w = xv.w * rsqrtf(a3);
        *reinterpret_cast<float4*>(xb + d*HW + p0 + j*4) = o;
    }
}

// ---- conv2 (f32x2, 4co x 8px/thread): 128->128, 5x5, s2. grid (64,4,2), 128 thr ----
__global__ void __launch_bounds__(128, 4) conv2_kernel(const float* __restrict__ w,
                                                       const float* __restrict__ b){
    __shared__ float sin_[5624];   // 8ci x 19 x 37
    __shared__ float sw[6400];     // 32co x 8ci x 25
    int bp = blockIdx.x, co0 = blockIdx.y*32, ry0 = blockIdx.z*8;
    int t = threadIdx.x;
    int pxg = t & 15, cg = t >> 4;            // cg 0..7 -> 4 co each
    int ly = pxg >> 1, lx0 = (pxg & 1)*8;     // 8 px per thread
    ull acc[4][4];
    #pragma unroll
    for (int i = 0; i < 4; i++){
        float bb = b[co0 + cg*4 + i];
        #pragma unroll
        for (int jj = 0; jj < 4; jj++) acc[i][jj] = pkdup(bb);
    }
    const float* xb = g_s1 + bp*131072;
    int iy0 = 2*ry0 - 2;
    for (int ci0 = 0; ci0 < 128; ci0 += 8){
        __syncthreads();
        for (int e = t; e < 5320; e += 128){
            int ci = e/665, rem = e - ci*665, r = rem/35, col = rem - r*35;
            int gy = iy0 + r, gx = col - 2;
            float v = 0.f;
            if (gy>=0 && gy<32 && gx>=0 && gx<32) v = xb[(ci0+ci)*1024 + gy*32 + gx];
            sin_[(ci*19 + r)*37 + col] = v;
        }
        for (int e = t; e < 6400; e += 128){
            int i = e/200, rem = e - i*200;
            sw[e] = w[(co0+i)*3200 + ci0*25 + rem];
        }
        __syncthreads();
        #pragma unroll 1
        for (int ci = 0; ci < 8; ci++){
            #pragma unroll 1
            for (int ky = 0; ky < 5; ky++){
                const float* srow = sin_ + (ci*19 + 2*ly + ky)*37 + 2*lx0;
                const float* wrow = sw + cg*4*200 + ci*25 + ky*5;
                #pragma unroll
                for (int kx = 0; kx < 5; kx++){
                    ull xp[4];
                    #pragma unroll
                    for (int jj = 0; jj < 4; jj++)
                        xp[jj] = pk2(srow[4*jj + kx], srow[4*jj + kx + 2]);
                    #pragma unroll
                    for (int i = 0; i < 4; i++){
                        ull wp = pkdup(wrow[i*200 + kx]);
                        #pragma unroll
                        for (int jj = 0; jj < 4; jj++)
                            acc[i][jj] = ffma2(xp[jj], wp, acc[i][jj]);
                    }
                }
            }
        }
    }
    float* ob = g_s2 + bp*32768;
    #pragma unroll
    for (int i = 0; i < 4; i++){
        float* orow = ob + (co0 + cg*4 + i)*256 + (ry0+ly)*16 + lx0;
        #pragma unroll
        for (int jj = 0; jj < 4; jj++)
            *reinterpret_cast<ull*>(orow + 2*jj) = acc[i][jj];
    }
}

// ---- conv3 (f32x2, 4co x 8px/thread): 128->192, 3x3, s1. grid (64,6,2), 128 thr ----
__global__ void __launch_bounds__(128, 4) conv3_kernel(const float* __restrict__ w,
                                                       const float* __restrict__ b){
    __shared__ float sin_[2100];   // 8ci x 10 x 21
    __shared__ float sw[2304];     // 32co x 8ci x 9
    int bp = blockIdx.x, co0 = blockIdx.y*32, ry0 = blockIdx.z*8;
    int t = threadIdx.x;
    int pxg = t & 15, cg = t >> 4;
    int ly = pxg >> 1, lx0 = (pxg & 1)*8;
    ull acc[4][4];
    #pragma unroll
    for (int i = 0; i < 4; i++){
        float bb = b[co0 + cg*4 + i];
        #pragma unroll
        for (int jj = 0; jj < 4; jj++) acc[i][jj] = pkdup(bb);
    }
    const float* xb = g_s2 + bp*32768;
    int iy0 = ry0 - 1;
    for (int ci0 = 0; ci0 < 128; ci0 += 8){
        __syncthreads();
        for (int e = t; e < 1440; e += 128){
            int ci = e/180, rem = e - ci*180, r = rem/18, col = rem - r*18;
            int gy = iy0 + r, gx = col - 1;
            float v = 0.f;
            if (gy>=0 && gy<16 && gx>=0 && gx<16) v = xb[(ci0+ci)*256 + gy*16 + gx];
            sin_[(ci*10 + r)*21 + col] = v;
        }
        for (int e = t; e < 2304; e += 128){
            int i = e/72, rem = e - i*72;
            sw[e] = w[(co0+i)*1152 + ci0*9 + rem];
        }
        __syncthreads();
        #pragma unroll 1
        for (int ci = 0; ci < 8; ci++){
            #pragma unroll 1
            for (int ky = 0; ky < 3; ky++){
                const float* srow = sin_ + (ci*10 + ly + ky)*21 + lx0;
                const float* wrow = sw + cg*4*72 + ci*9 + ky*3;
                #pragma unroll
                for (int kx = 0; kx < 3; kx++){
                    ull xp[4];
                    #pragma unroll
                    for (int jj = 0; jj < 4; jj++)
                        xp[jj] = pk2(srow[2*jj + kx], srow[2*jj + kx + 1]);
                    #pragma unroll
                    for (int i = 0; i < 4; i++){
                        ull wp = pkdup(wrow[i*72 + kx]);
                        #pragma unroll
                        for (int jj = 0; jj < 4; jj++)
                            acc[i][jj] = ffma2(xp[jj], wp, acc[i][jj]);
                    }
                }
            }
        }
    }
    float* ob = g_y3 + bp*49152;
    #pragma unroll
    for (int i = 0; i < 4; i++){
        float* orow = ob + (co0 + cg*4 + i)*256 + (ry0+ly)*16 + lx0;
        #pragma unroll
        for (int jj = 0; jj < 4; jj++)
            *reinterpret_cast<ull*>(orow + 2*jj) = acc[i][jj];
    }
}

// ---- kv: LN + k_proj + v_proj. grid 64, 256 thr ----
__global__ void kv_kernel(const float* __restrict__ yg, const float* __restrict__ lnw,
                          const float* __restrict__ lnb, const float* __restrict__ Wk,
                          const float* __restrict__ Wv){
    __shared__ float s_kv[32*193];
    __shared__ float s_w[64*33];
    int bp = blockIdx.x;
    int t = threadIdx.x;
    int w = t >> 5, l = t & 31;
    for (int e = t; e < 6144; e += 256){
        int c = e >> 5, k = e & 31;
        s_kv[k*193 + c] = yg[bp*6144 + c*32 + k];
    }
    __syncthreads();
    {
        float lwv[6], lbv[6];
        #pragma unroll
        for (int i = 0; i < 6; i++){ lwv[i] = lnw[l+32*i]; lbv[i] = lnb[l+32*i]; }
        for (int ki = 0; ki < 4; ki++){
            int k = w*4 + ki;
            float v[6]; float s = 0.f;
            #pragma unroll
            for (int i = 0; i < 6; i++){ v[i] = s_kv[k*193 + l + 32*i]; s += v[i]; }
            #pragma unroll
            for (int o = 16; o > 0; o >>= 1) s += __shfl_xor_sync(0xffffffffu, s, o);
            float mu = s * (1.f/192.f);
            float vs = 0.f;
            #pragma unroll
            for (int i = 0; i < 6; i++){ float d = v[i]-mu; vs += d*d; }
            #pragma unroll
            for (int o = 16; o > 0; o >>= 1) vs += __shfl_xor_sync(0xffffffffu, vs, o);
            float rs = rsqrtf(vs * (1.f/192.f) + LN_EPS);
            #pragma unroll
            for (int i = 0; i < 6; i++)
                s_kv[k*193 + l + 32*i] = (v[i]-mu)*rs*lwv[i] + lbv[i];
        }
    }
    int kq = t & 7, rp = t >> 3;
    for (int r0 = 0; r0 < 320; r0 += 64){
        float acc[2][4];
        #pragma unroll
        for (int i = 0; i < 2; i++)
            #pragma unroll
            for (int kk = 0; kk < 4; kk++) acc[i][kk] = 0.f;
        for (int c0 = 0; c0 < 192; c0 += 32){
            __syncthreads();
            for (int e = t; e < 2048; e += 256){
                int rr = e >> 5, cc = e & 31;
                int row = r0 + rr;
                s_w[rr*33 + cc] = (row < 128) ? Wk[row*192 + c0 + cc]
                                              : Wv[(row-128)*192 + c0 + cc];
            }
            __syncthreads();
            for (int cc = 0; cc < 32; cc++){
                float wv0 = s_w[(rp*2)*33 + cc], wv1 = s_w[(rp*2+1)*33 + cc];
                #pragma unroll
                for (int kk = 0; kk < 4; kk++){
                    float kvv = s_kv[(kq*4+kk)*193 + c0 + cc];
                    acc[0][kk] = fmaf(wv0, kvv, acc[0][kk]);
                    acc[1][kk] = fmaf(wv1, kvv, acc[1][kk]);
                }
            }
        }
        #pragma unroll
        for (int i = 0; i < 2; i++){
            int row = r0 + rp*2 + i;
            #pragma unroll
            for (int kk = 0; kk < 4; kk++){
                int k = kq*4 + kk;
                if (row < 128) g_kp[bp*4096 + k*128 + row] = acc[i][kk];
                else           g_vp[bp*6144 + k*192 + (row-128)] = acc[i][kk];
            }
        }
    }
}

// ---- attention: grid 512, 256 thr, 95872 B dyn smem ----
__global__ void attn_kernel(const float* __restrict__ lnqw, const float* __restrict__ lnqb,
                            const float* __restrict__ Wq, const float* __restrict__ vw,
                            const float* __restrict__ out_w, const float* __restrict__ out_b,
                            const float* __restrict__ lnow, const float* __restrict__ lnob,
                            float* __restrict__ out){
    extern __shared__ float sm[];
    float* s_qn  = sm;
    float* s_w   = sm + 6176;
    float* s_kp  = sm + 12512;
    float* s_e   = sm + 16736;
    float* s_ctx = sm + 17792;
    int bp = blockIdx.x >> 3;
    int q0 = (blockIdx.x & 7) << 5;
    int t = threadIdx.x;
    int w = t >> 5, l = t & 31;
    const float* y3 = g_y3 + bp*49152;
    for (int e = t; e < 6144; e += 256){
        int m = e >> 5, q = e & 31;
        s_qn[q*193 + m] = y3[m*256 + q0 + q];
    }
    for (int e = t; e < 4096; e += 256){
        int k = e >> 7;
        s_kp[k*132 + (e & 127)] = g_kp[bp*4096 + e];
    }
    __syncthreads();
    {
        float lwv[6], lbv[6];
        #pragma unroll
        for (int i = 0; i < 6; i++){ lwv[i] = lnqw[l+32*i]; lbv[i] = lnqb[l+32*i]; }
        for (int qi = 0; qi < 4; qi++){
            int q = w*4 + qi;
            float v[6]; float s = 0.f;
            #pragma unroll
            for (int i = 0; i < 6; i++){ v[i] = s_qn[q*193 + l + 32*i]; s += v[i]; }
            #pragma unroll
            for (int o = 16; o > 0; o >>= 1) s += __shfl_xor_sync(0xffffffffu, s, o);
            float mu = s * (1.f/192.f);
            float vs = 0.f;
            #pragma unroll
            for (int i = 0; i < 6; i++){ float d = v[i]-mu; vs += d*d; }
            #pragma unroll
            for (int o = 16; o > 0; o >>= 1) vs += __shfl_xor_sync(0xffffffffu, vs, o);
            float rs = rsqrtf(vs * (1.f/192.f) + LN_EPS);
            #pragma unroll
            for (int i = 0; i < 6; i++)
                s_qn[q*193 + l + 32*i] = (v[i]-mu)*rs*lwv[i] + lbv[i];
        }
    }
    float qp[4][4];
    #pragma unroll
    for (int a = 0; a < 4; a++)
        #pragma unroll
        for (int b2 = 0; b2 < 4; b2++) qp[a][b2] = 0.f;
    for (int c0 = 0; c0 < 192; c0 += 32){
        __syncthreads();
        for (int e = t; e < 4096; e += 256){
            int d = e >> 5, cc = e & 31;
            s_w[d*33 + cc] = Wq[d*192 + c0 + cc];
        }
        __syncthreads();
        for (int cc = 0; cc < 32; cc++){
            float wv[4], qv[4];
            #pragma unroll
            for (int j = 0; j < 4; j++) wv[j] = s_w[(l+32*j)*33 + cc];
            #pragma unroll
            for (int qi = 0; qi < 4; qi++) qv[qi] = s_qn[(w*4+qi)*193 + c0 + cc];
            #pragma unroll
            for (int qi = 0; qi < 4; qi++)
                #pragma unroll
                for (int j = 0; j < 4; j++) qp[qi][j] = fmaf(qv[qi], wv[j], qp[qi][j]);
        }
    }
    __syncthreads();
    float* s_vp = s_w;
    for (int e = t; e < 6144; e += 256){
        int k = e / 192, m = e - k*192;
        s_vp[k*193 + m] = g_vp[bp*6144 + e];
    }
    float vv[4];
    #pragma unroll
    for (int j = 0; j < 4; j++) vv[j] = vw[l + 32*j];
    for (int k = 0; k < 32; k++){
        float kp4[4];
        #pragma unroll
        for (int j = 0; j < 4; j++) kp4[j] = s_kp[k*132 + l + 32*j];
        #pragma unroll
        for (int qi = 0; qi < 4; qi++){
            float s = 0.f;
            #pragma unroll
            for (int j = 0; j < 4; j++)
                s = fmaf(tanh_fast(qp[qi][j] + kp4[j]), vv[j], s);
            #pragma unroll
            for (int o = 16; o > 0; o >>= 1) s += __shfl_xor_sync(0xffffffffu, s, o);
            if (l == 0) s_e[(w*4+qi)*33 + k] = s;
        }
    }
    __syncwarp();
    for (int qi = 0; qi < 4; qi++){
        int q = w*4 + qi;
        float ev = s_e[q*33 + l];
        float mx = ev;
        #pragma unroll
        for (int o = 16; o > 0; o >>= 1) mx = fmaxf(mx, __shfl_xor_sync(0xffffffffu, mx, o));
        float p = __expf(ev - mx);
        float s = p;
        #pragma unroll
        for (int o = 16; o > 0; o >>= 1) s += __shfl_xor_sync(0xffffffffu, s, o);
        s_e[q*33 + l] = p / s;
    }
    __syncthreads();
    {
        int qr = t >> 3, mg = t & 7;
        float acc[24];
        #pragma unroll
        for (int i = 0; i < 24; i++) acc[i] = 0.f;
        for (int k = 0; k < 32; k++){
            float a = s_e[qr*33 + k];
            #pragma unroll
            for (int i = 0; i < 24; i++)
                acc[i] = fmaf(a, s_vp[k*193 + mg + 8*i], acc[i]);
        }
        #pragma unroll
        for (int i = 0; i < 24; i++) s_ctx[qr*193 + mg + 8*i] = acc[i];
    }
    __syncthreads();
    {
        int qh = t >> 4, ng = t & 15;
        float acc0[12], acc1[12];
        #pragma unroll
        for (int i = 0; i < 12; i++){ acc0[i] = 0.f; acc1[i] = 0.f; }
        for (int m0 = 0; m0 < 192; m0 += 32){
            __syncthreads();
            for (int e = t; e < 6144; e += 256){
                int n = e >> 5, mm = e & 31;
                s_w[n*33 + mm] = out_w[n*192 + m0 + mm];
            }
            __syncthreads();
            for (int mm = 0; mm < 32; mm++){
                float c0v = s_ctx[(2*qh)*193 + m0 + mm];
                float c1v = s_ctx[(2*qh+1)*193 + m0 + mm];
                #pragma unroll
                for (int i = 0; i < 12; i++){
                    float wv = s_w[(ng+16*i)*33 + mm];
                    acc0[i] = fmaf(c0v, wv, acc0[i]);
                    acc1[i] = fmaf(c1v, wv, acc1[i]);
                }
            }
        }
        float val0[12], val1[12];
        float s0 = 0.f, s1 = 0.f;
        #pragma unroll
        for (int i = 0; i < 12; i++){
            int n = ng + 16*i;
            val0[i] = acc0[i] + out_b[n] + s_qn[(2*qh)*193 + n];
            val1[i] = acc1[i] + out_b[n] + s_qn[(2*qh+1)*193 + n];
            s0 += val0[i]; s1 += val1[i];
        }
        #pragma unroll
        for (int o = 8; o > 0; o >>= 1){
            s0 += __shfl_xor_sync(0xffffffffu, s0, o);
            s1 += __shfl_xor_sync(0xffffffffu, s1, o);
        }
        float mu0 = s0*(1.f/192.f), mu1 = s1*(1.f/192.f);
        float vs0 = 0.f, vs1 = 0.f;
        #pragma unroll
        for (int i = 0; i < 12; i++){
            float d0 = val0[i]-mu0, d1 = val1[i]-mu1;
            vs0 += d0*d0; vs1 += d1*d1;
        }
        #pragma unroll
        for (int o = 8; o > 0; o >>= 1){
            vs0 += __shfl_xor_sync(0xffffffffu, vs0, o);
            vs1 += __shfl_xor_sync(0xffffffffu, vs1, o);
        }
        float r0 = rsqrtf(vs0*(1.f/192.f) + LN_EPS);
        float r1 = rsqrtf(vs1*(1.f/192.f) + LN_EPS);
        __syncthreads();
        #pragma unroll
        for (int i = 0; i < 12; i++){
            int n = ng + 16*i;
            s_ctx[(2*qh)*193 + n]   = (val0[i]-mu0)*r0*lnow[n] + lnob[n];
            s_ctx[(2*qh+1)*193 + n] = (val1[i]-mu1)*r1*lnow[n] + lnob[n];
        }
    }
    __syncthreads();
    for (int e = t; e < 6144; e += 256){
        int n = e >> 5, q = e & 31;
        out[bp*49152 + n*256 + q0 + q] = s_ctx[q*193 + n];
    }
}

extern "C" void kernel_launch(void* const* d_in, const int* in_sizes, int n_in,
                              void* d_out, int out_size){
    const float* x_p    = (const float*)d_in[0];
    const float* y_g    = (const float*)d_in[1];
    const float* conv1w = (const float*)d_in[2];
    const float* conv1b = (const float*)d_in[3];
    const float* gamma1 = (const float*)d_in[4];
    const float* beta1  = (const float*)d_in[5];
    const float* conv2w = (const float*)d_in[6];
    const float* conv2b = (const float*)d_in[7];
    const float* gamma2 = (const float*)d_in[8];
    const float* beta2  = (const float*)d_in[9];
    const float* conv3w = (const float*)d_in[10];
    const float* conv3b = (const float*)d_in[11];
    const float* lnqw   = (const float*)d_in[12];
    const float* lnqb   = (const float*)d_in[13];
    const float* lnkw   = (const float*)d_in[14];
    const float* lnkb   = (const float*)d_in[15];
    const float* lnow   = (const float*)d_in[16];
    const float* lnob   = (const float*)d_in[17];
    const float* Wq     = (const float*)d_in[18];
    const float* Wk     = (const float*)d_in[19];
    const float* vw     = (const float*)d_in[20];
    const float* Wv     = (const float*)d_in[21];
    const float* outw   = (const float*)d_in[22];
    const float* outb   = (const float*)d_in[23];
    float* out = (float*)d_out;

    cudaFuncSetAttribute(attn_kernel, cudaFuncAttributeMaxDynamicSharedMemorySize, 98304);
    cudaFuncSetAttribute(conv2_kernel, cudaFuncAttributePreferredSharedMemoryCarveout, 90);

    prep_kernel<<<128, 256>>>(gamma1, gamma2);
    conv1_kernel<<<dim3(64,4,2), 256>>>(x_p, conv1w, conv1b);
    gdn_kernel<<<1024, 256>>>(1, beta1);
    conv2_kernel<<<dim3(64,4,2), 128>>>(conv2w, conv2b);
    gdn_kernel<<<256, 256>>>(2, beta2);
    conv3_kernel<<<dim3(64,6,2), 128>>>(conv3w, conv3b);
    kv_kernel<<<64, 256>>>(y_g, lnkw, lnkb, Wk, Wv);
    attn_kernel<<<512, 256, 95872>>>(lnqw, lnqb, Wq, vw, outw, outb, lnow, lnob, out);
}

// round 5
// speedup vs baseline: 1.0749x; 1.0083x over previous
#include <cuda_runtime.h>

#define LN_EPS 1e-5f
typedef unsigned long long ull;

// ---- scratch ----
__device__ float g_s1[64*128*1024];
__device__ float g_s2[64*128*256];
__device__ float g_y3[64*192*256];
__device__ float g_kp[64*32*128];
__device__ float g_vp[64*32*192];
__device__ float g_gT[2][16384];

__device__ __forceinline__ float tanh_fast(float x){
    float y; asm("tanh.approx.f32 %0, %1;" : "=f"(y) : "f"(x)); return y;
}
__device__ __forceinline__ ull pk2(float lo, float hi){
    ull r; asm("mov.b64 %0, {%1, %2};" : "=l"(r) : "f"(lo), "f"(hi)); return r;
}
__device__ __forceinline__ ull pkdup(float v){ return pk2(v, v); }
__device__ __forceinline__ void upk2(ull p, float& lo, float& hi){
    asm("mov.b64 {%0, %1}, %2;" : "=f"(lo), "=f"(hi) : "l"(p));
}
__device__ __forceinline__ ull ffma2(ull a, ull b, ull c){
    ull d; asm("fma.rn.f32x2 %0, %1, %2, %3;" : "=l"(d) : "l"(a), "l"(b), "l"(c)); return d;
}

// ---- prep: transpose gammas ----
__global__ void prep_kernel(const float* __restrict__ g1, const float* __restrict__ g2){
    int bwhich = blockIdx.x >> 6;
    int e = ((blockIdx.x & 63) << 8) + threadIdx.x;
    const float* g = bwhich ? g2 : g1;
    int d = e >> 7, c = e & 127;
    g_gT[bwhich][c*128 + d] = g[e];
}

// ---- conv1: 3->128, 5x5, s2, p2 (64x64 -> 32x32). grid (64,4,2), 256 thr ----
__global__ void conv1_kernel(const float* __restrict__ x, const float* __restrict__ w,
                             const float* __restrict__ b){
    __shared__ float sw[4800];
    __shared__ float sin_[3885];
    int bp = blockIdx.x, tile = blockIdx.y, z = blockIdx.z;
    int t = threadIdx.x;
    for (int e = t; e < 4800; e += 256) sw[e] = w[z*4800 + e];
    int ty0 = (tile>>1)*16, tx0 = (tile&1)*16;
    int iy0 = 2*ty0 - 2, ix0 = 2*tx0 - 2;
    const float* xb = x + bp*12288;
    for (int e = t; e < 3675; e += 256){
        int c = e/1225, rem = e - c*1225, r = rem/35, col = rem - r*35;
        int gy = iy0 + r, gx = ix0 + col;
        float v = 0.f;
        if (gy>=0 && gy<64 && gx>=0 && gx<64) v = xb[c*4096 + gy*64 + gx];
        sin_[(c*35 + r)*37 + col] = v;
    }
    __syncthreads();
    int px4 = t & 63, cog = t >> 6;
    int ly = px4 >> 2, lx0 = (px4 & 3)*4;
    float* ob = g_s1 + bp*131072;
    for (int p = 0; p < 2; p++){
        int col0 = cog*16 + p*8;
        float acc[8][4];
        #pragma unroll
        for (int i = 0; i < 8; i++){
            float bb = b[z*64 + col0 + i];
            #pragma unroll
            for (int j = 0; j < 4; j++) acc[i][j] = bb;
        }
        #pragma unroll 1
        for (int c = 0; c < 3; c++){
            #pragma unroll
            for (int ky = 0; ky < 5; ky++){
                #pragma unroll
                for (int kx = 0; kx < 5; kx++){
                    float xv[4];
                    #pragma unroll
                    for (int j = 0; j < 4; j++)
                        xv[j] = sin_[(c*35 + 2*ly + ky)*37 + 2*lx0 + 2*j + kx];
                    #pragma unroll
                    for (int i = 0; i < 8; i++){
                        float wv = sw[(col0+i)*75 + c*25 + ky*5 + kx];
                        #pragma unroll
                        for (int j = 0; j < 4; j++) acc[i][j] = fmaf(wv, xv[j], acc[i][j]);
                    }
                }
            }
        }
        #pragma unroll
        for (int i = 0; i < 8; i++){
            float4 o = make_float4(acc[i][0], acc[i][1], acc[i][2], acc[i][3]);
            *reinterpret_cast<float4*>(ob + (z*64+col0+i)*1024 + (ty0+ly)*32 + tx0 + lx0) = o;
        }
    }
}

// ---- GDN in-place (f32x2). grid BP*HW/64, 256 thr ----
__global__ void gdn_kernel(int stage, const float* __restrict__ beta){
    __shared__ float sA[2048];
    __shared__ float sB[1088];
    int HW = (stage == 1) ? 1024 : 256;
    float* x = (stage == 1) ? g_s1 : g_s2;
    const float* gT = g_gT[stage-1];
    int chunks = HW >> 6;
    int bp = blockIdx.x / chunks;
    int p0 = (blockIdx.x - bp*chunks) * 64;
    int t = threadIdx.x;
    int i = t >> 4, j = t & 15;
    float* xb = x + bp*128*HW;
    ull acc[8][2];
    #pragma unroll
    for (int ii = 0; ii < 8; ii++){
        float bb = beta[i*8 + ii];
        acc[ii][0] = pkdup(bb); acc[ii][1] = pkdup(bb);
    }
    for (int c0 = 0; c0 < 128; c0 += 16){
        __syncthreads();
        for (int e = t; e < 2048; e += 256) sA[e] = gT[c0*128 + e];
        for (int e = t; e < 1024; e += 256){
            int cc = e >> 6, p = e & 63;
            float v = xb[(c0+cc)*HW + p0 + p];
            sB[cc*68 + p] = v*v;
        }
        __syncthreads();
        #pragma unroll
        for (int cc = 0; cc < 16; cc++){
            const ull* xp = reinterpret_cast<const ull*>(sB + cc*68 + j*4);
            ull x0 = xp[0], x1 = xp[1];
            float4 ga = *reinterpret_cast<const float4*>(sA + cc*128 + i*8);
            float4 gb = *reinterpret_cast<const float4*>(sA + cc*128 + i*8 + 4);
            float gs[8] = {ga.x,ga.y,ga.z,ga.w,gb.x,gb.y,gb.z,gb.w};
            #pragma unroll
            for (int ii = 0; ii < 8; ii++){
                ull wp = pkdup(gs[ii]);
                acc[ii][0] = ffma2(x0, wp, acc[ii][0]);
                acc[ii][1] = ffma2(x1, wp, acc[ii][1]);
            }
        }
    }
    #pragma unroll
    for (int ii = 0; ii < 8; ii++){
        int d = i*8 + ii;
        float a0,a1,a2,a3;
        upk2(acc[ii][0], a0, a1);
        upk2(acc[ii][1], a2, a3);
        float4 xv = *reinterpret_cast<const float4*>(xb + d*HW + p0 + j*4);
        float4 o;
        o.x = xv.x * rsqrtf(a0);
        o.y = xv.y * rsqrtf(a1);
        o.z = xv.z * rsqrtf(a2);
        o.w = xv.w * rsqrtf(a3);
        *reinterpret_cast<float4*>(xb + d*HW + p0 + j*4) = o;
    }
}

// ---- conv2 (f32x2, 4co x 4px/thread): 128->128, 5x5, s2. grid (64,8,2), 128 thr ----
__global__ void __launch_bounds__(128) conv2_kernel(const float* __restrict__ w,
                                                    const float* __restrict__ b){
    __shared__ float sin_[5624];   // 8ci x 19 x 37
    __shared__ float sw[3200];     // 16co x 8ci x 25
    int bp = blockIdx.x, co0 = blockIdx.y*16, ry0 = blockIdx.z*8;
    int t = threadIdx.x;
    int pxg = t & 31, cg = t >> 5;            // cg 0..3 -> 4 co each
    int ly = pxg >> 2, lx0 = (pxg & 3)*4;     // 8 rows x 4 px
    ull acc[4][2];
    #pragma unroll
    for (int i = 0; i < 4; i++){
        float bb = b[co0 + cg*4 + i];
        acc[i][0] = pkdup(bb); acc[i][1] = pkdup(bb);
    }
    const float* xb = g_s1 + bp*131072;
    int iy0 = 2*ry0 - 2;
    for (int ci0 = 0; ci0 < 128; ci0 += 8){
        __syncthreads();
        for (int e = t; e < 5320; e += 128){
            int ci = e/665, rem = e - ci*665, r = rem/35, col = rem - r*35;
            int gy = iy0 + r, gx = col - 2;
            float v = 0.f;
            if (gy>=0 && gy<32 && gx>=0 && gx<32) v = xb[(ci0+ci)*1024 + gy*32 + gx];
            sin_[(ci*19 + r)*37 + col] = v;
        }
        for (int e = t; e < 3200; e += 128){
            int i = e/200, rem = e - i*200;
            sw[e] = w[(co0+i)*3200 + ci0*25 + rem];
        }
        __syncthreads();
        #pragma unroll 1
        for (int ci = 0; ci < 8; ci++){
            #pragma unroll 1
            for (int ky = 0; ky < 5; ky++){
                const float* srow = sin_ + (ci*19 + 2*ly + ky)*37 + 2*lx0;
                const float* wrow = sw + cg*4*200 + ci*25 + ky*5;
                #pragma unroll
                for (int kx = 0; kx < 5; kx++){
                    ull xp0 = pk2(srow[kx], srow[kx + 2]);
                    ull xp1 = pk2(srow[kx + 4], srow[kx + 6]);
                    #pragma unroll
                    for (int i = 0; i < 4; i++){
                        ull wp = pkdup(wrow[i*200 + kx]);
                        acc[i][0] = ffma2(xp0, wp, acc[i][0]);
                        acc[i][1] = ffma2(xp1, wp, acc[i][1]);
                    }
                }
            }
        }
    }
    float* ob = g_s2 + bp*32768;
    #pragma unroll
    for (int i = 0; i < 4; i++){
        float* orow = ob + (co0 + cg*4 + i)*256 + (ry0+ly)*16 + lx0;
        *reinterpret_cast<ull*>(orow)     = acc[i][0];
        *reinterpret_cast<ull*>(orow + 2) = acc[i][1];
    }
}

// ---- conv3 (f32x2, 4co x 4px/thread): 128->192, 3x3, s1. grid (64,12,2), 128 thr ----
__global__ void __launch_bounds__(128) conv3_kernel(const float* __restrict__ w,
                                                    const float* __restrict__ b){
    __shared__ float sin_[2100];   // 8ci x 10 x 21
    __shared__ float sw[1152];     // 16co x 8ci x 9
    int bp = blockIdx.x, co0 = blockIdx.y*16, ry0 = blockIdx.z*8;
    int t = threadIdx.x;
    int pxg = t & 31, cg = t >> 5;
    int ly = pxg >> 2, lx0 = (pxg & 3)*4;
    ull acc[4][2];
    #pragma unroll
    for (int i = 0; i < 4; i++){
        float bb = b[co0 + cg*4 + i];
        acc[i][0] = pkdup(bb); acc[i][1] = pkdup(bb);
    }
    const float* xb = g_s2 + bp*32768;
    int iy0 = ry0 - 1;
    for (int ci0 = 0; ci0 < 128; ci0 += 8){
        __syncthreads();
        for (int e = t; e < 1440; e += 128){
            int ci = e/180, rem = e - ci*180, r = rem/18, col = rem - r*18;
            int gy = iy0 + r, gx = col - 1;
            float v = 0.f;
            if (gy>=0 && gy<16 && gx>=0 && gx<16) v = xb[(ci0+ci)*256 + gy*16 + gx];
            sin_[(ci*10 + r)*21 + col] = v;
        }
        for (int e = t; e < 1152; e += 128){
            int i = e/72, rem = e - i*72;
            sw[e] = w[(co0+i)*1152 + ci0*9 + rem];
        }
        __syncthreads();
        #pragma unroll 1
        for (int ci = 0; ci < 8; ci++){
            #pragma unroll 1
            for (int ky = 0; ky < 3; ky++){
                const float* srow = sin_ + (ci*10 + ly + ky)*21 + lx0;
                const float* wrow = sw + cg*4*72 + ci*9 + ky*3;
                #pragma unroll
                for (int kx = 0; kx < 3; kx++){
                    ull xp0 = pk2(srow[kx], srow[kx + 1]);
                    ull xp1 = pk2(srow[kx + 2], srow[kx + 3]);
                    #pragma unroll
                    for (int i = 0; i < 4; i++){
                        ull wp = pkdup(wrow[i*72 + kx]);
                        acc[i][0] = ffma2(xp0, wp, acc[i][0]);
                        acc[i][1] = ffma2(xp1, wp, acc[i][1]);
                    }
                }
            }
        }
    }
    float* ob = g_y3 + bp*49152;
    #pragma unroll
    for (int i = 0; i < 4; i++){
        float* orow = ob + (co0 + cg*4 + i)*256 + (ry0+ly)*16 + lx0;
        *reinterpret_cast<ull*>(orow)     = acc[i][0];
        *reinterpret_cast<ull*>(orow + 2) = acc[i][1];
    }
}

// ---- kv: LN + k_proj + v_proj. grid (64,5), 256 thr ----
__global__ void kv_kernel(const float* __restrict__ yg, const float* __restrict__ lnw,
                          const float* __restrict__ lnb, const float* __restrict__ Wk,
                          const float* __restrict__ Wv){
    __shared__ float s_kv[32*193];
    __shared__ float s_w[64*33];
    int bp = blockIdx.x;
    int r0 = blockIdx.y * 64;
    int t = threadIdx.x;
    int w = t >> 5, l = t & 31;
    for (int e = t; e < 6144; e += 256){
        int c = e >> 5, k = e & 31;
        s_kv[k*193 + c] = yg[bp*6144 + c*32 + k];
    }
    __syncthreads();
    {
        float lwv[6], lbv[6];
        #pragma unroll
        for (int i = 0; i < 6; i++){ lwv[i] = lnw[l+32*i]; lbv[i] = lnb[l+32*i]; }
        for (int ki = 0; ki < 4; ki++){
            int k = w*4 + ki;
            float v[6]; float s = 0.f;
            #pragma unroll
            for (int i = 0; i < 6; i++){ v[i] = s_kv[k*193 + l + 32*i]; s += v[i]; }
            #pragma unroll
            for (int o = 16; o > 0; o >>= 1) s += __shfl_xor_sync(0xffffffffu, s, o);
            float mu = s * (1.f/192.f);
            float vs = 0.f;
            #pragma unroll
            for (int i = 0; i < 6; i++){ float d = v[i]-mu; vs += d*d; }
            #pragma unroll
            for (int o = 16; o > 0; o >>= 1) vs += __shfl_xor_sync(0xffffffffu, vs, o);
            float rs = rsqrtf(vs * (1.f/192.f) + LN_EPS);
            #pragma unroll
            for (int i = 0; i < 6; i++)
                s_kv[k*193 + l + 32*i] = (v[i]-mu)*rs*lwv[i] + lbv[i];
        }
    }
    int kq = t & 7, rp = t >> 3;
    {
        float acc[2][4];
        #pragma unroll
        for (int i = 0; i < 2; i++)
            #pragma unroll
            for (int kk = 0; kk < 4; kk++) acc[i][kk] = 0.f;
        for (int c0 = 0; c0 < 192; c0 += 32){
            __syncthreads();
            for (int e = t; e < 2048; e += 256){
                int rr = e >> 5, cc = e & 31;
                int row = r0 + rr;
                s_w[rr*33 + cc] = (row < 128) ? Wk[row*192 + c0 + cc]
                                              : Wv[(row-128)*192 + c0 + cc];
            }
            __syncthreads();
            for (int cc = 0; cc < 32; cc++){
                float wv0 = s_w[(rp*2)*33 + cc], wv1 = s_w[(rp*2+1)*33 + cc];
                #pragma unroll
                for (int kk = 0; kk < 4; kk++){
                    float kvv = s_kv[(kq*4+kk)*193 + c0 + cc];
                    acc[0][kk] = fmaf(wv0, kvv, acc[0][kk]);
                    acc[1][kk] = fmaf(wv1, kvv, acc[1][kk]);
                }
            }
        }
        #pragma unroll
        for (int i = 0; i < 2; i++){
            int row = r0 + rp*2 + i;
            #pragma unroll
            for (int kk = 0; kk < 4; kk++){
                int k = kq*4 + kk;
                if (row < 128) g_kp[bp*4096 + k*128 + row] = acc[i][kk];
                else           g_vp[bp*6144 + k*192 + (row-128)] = acc[i][kk];
            }
        }
    }
}

// ---- attention: grid 512, 256 thr, 95872 B dyn smem ----
__global__ void attn_kernel(const float* __restrict__ lnqw, const float* __restrict__ lnqb,
                            const float* __restrict__ Wq, const float* __restrict__ vw,
                            const float* __restrict__ out_w, const float* __restrict__ out_b,
                            const float* __restrict__ lnow, const float* __restrict__ lnob,
                            float* __restrict__ out){
    extern __shared__ float sm[];
    float* s_qn  = sm;
    float* s_w   = sm + 6176;
    float* s_kp  = sm + 12512;
    float* s_e   = sm + 16736;
    float* s_ctx = sm + 17792;
    int bp = blockIdx.x >> 3;
    int q0 = (blockIdx.x & 7) << 5;
    int t = threadIdx.x;
    int w = t >> 5, l = t & 31;
    const float* y3 = g_y3 + bp*49152;
    for (int e = t; e < 6144; e += 256){
        int m = e >> 5, q = e & 31;
        s_qn[q*193 + m] = y3[m*256 + q0 + q];
    }
    for (int e = t; e < 4096; e += 256){
        int k = e >> 7;
        s_kp[k*132 + (e & 127)] = g_kp[bp*4096 + e];
    }
    __syncthreads();
    {
        float lwv[6], lbv[6];
        #pragma unroll
        for (int i = 0; i < 6; i++){ lwv[i] = lnqw[l+32*i]; lbv[i] = lnqb[l+32*i]; }
        for (int qi = 0; qi < 4; qi++){
            int q = w*4 + qi;
            float v[6]; float s = 0.f;
            #pragma unroll
            for (int i = 0; i < 6; i++){ v[i] = s_qn[q*193 + l + 32*i]; s += v[i]; }
            #pragma unroll
            for (int o = 16; o > 0; o >>= 1) s += __shfl_xor_sync(0xffffffffu, s, o);
            float mu = s * (1.f/192.f);
            float vs = 0.f;
            #pragma unroll
            for (int i = 0; i < 6; i++){ float d = v[i]-mu; vs += d*d; }
            #pragma unroll
            for (int o = 16; o > 0; o >>= 1) vs += __shfl_xor_sync(0xffffffffu, vs, o);
            float rs = rsqrtf(vs * (1.f/192.f) + LN_EPS);
            #pragma unroll
            for (int i = 0; i < 6; i++)
                s_qn[q*193 + l + 32*i] = (v[i]-mu)*rs*lwv[i] + lbv[i];
        }
    }
    float qp[4][4];
    #pragma unroll
    for (int a = 0; a < 4; a++)
        #pragma unroll
        for (int b2 = 0; b2 < 4; b2++) qp[a][b2] = 0.f;
    for (int c0 = 0; c0 < 192; c0 += 32){
        __syncthreads();
        for (int e = t; e < 4096; e += 256){
            int d = e >> 5, cc = e & 31;
            s_w[d*33 + cc] = Wq[d*192 + c0 + cc];
        }
        __syncthreads();
        for (int cc = 0; cc < 32; cc++){
            float wv[4], qv[4];
            #pragma unroll
            for (int j = 0; j < 4; j++) wv[j] = s_w[(l+32*j)*33 + cc];
            #pragma unroll
            for (int qi = 0; qi < 4; qi++) qv[qi] = s_qn[(w*4+qi)*193 + c0 + cc];
            #pragma unroll
            for (int qi = 0; qi < 4; qi++)
                #pragma unroll
                for (int j = 0; j < 4; j++) qp[qi][j] = fmaf(qv[qi], wv[j], qp[qi][j]);
        }
    }
    __syncthreads();
    float* s_vp = s_w;
    for (int e = t; e < 6144; e += 256){
        int k = e / 192, m = e - k*192;
        s_vp[k*193 + m] = g_vp[bp*6144 + e];
    }
    float vv[4];
    #pragma unroll
    for (int j = 0; j < 4; j++) vv[j] = vw[l + 32*j];
    for (int k = 0; k < 32; k++){
        float kp4[4];
        #pragma unroll
        for (int j = 0; j < 4; j++) kp4[j] = s_kp[k*132 + l + 32*j];
        #pragma unroll
        for (int qi = 0; qi < 4; qi++){
            float s = 0.f;
            #pragma unroll
            for (int j = 0; j < 4; j++)
                s = fmaf(tanh_fast(qp[qi][j] + kp4[j]), vv[j], s);
            #pragma unroll
            for (int o = 16; o > 0; o >>= 1) s += __shfl_xor_sync(0xffffffffu, s, o);
            if (l == 0) s_e[(w*4+qi)*33 + k] = s;
        }
    }
    __syncwarp();
    for (int qi = 0; qi < 4; qi++){
        int q = w*4 + qi;
        float ev = s_e[q*33 + l];
        float mx = ev;
        #pragma unroll
        for (int o = 16; o > 0; o >>= 1) mx = fmaxf(mx, __shfl_xor_sync(0xffffffffu, mx, o));
        float p = __expf(ev - mx);
        float s = p;
        #pragma unroll
        for (int o = 16; o > 0; o >>= 1) s += __shfl_xor_sync(0xffffffffu, s, o);
        s_e[q*33 + l] = p / s;
    }
    __syncthreads();
    {
        int qr = t >> 3, mg = t & 7;
        float acc[24];
        #pragma unroll
        for (int i = 0; i < 24; i++) acc[i] = 0.f;
        for (int k = 0; k < 32; k++){
            float a = s_e[qr*33 + k];
            #pragma unroll
            for (int i = 0; i < 24; i++)
                acc[i] = fmaf(a, s_vp[k*193 + mg + 8*i], acc[i]);
        }
        #pragma unroll
        for (int i = 0; i < 24; i++) s_ctx[qr*193 + mg + 8*i] = acc[i];
    }
    __syncthreads();
    {
        int qh = t >> 4, ng = t & 15;
        float acc0[12], acc1[12];
        #pragma unroll
        for (int i = 0; i < 12; i++){ acc0[i] = 0.f; acc1[i] = 0.f; }
        for (int m0 = 0; m0 < 192; m0 += 32){
            __syncthreads();
            for (int e = t; e < 6144; e += 256){
                int n = e >> 5, mm = e & 31;
                s_w[n*33 + mm] = out_w[n*192 + m0 + mm];
            }
            __syncthreads();
            for (int mm = 0; mm < 32; mm++){
                float c0v = s_ctx[(2*qh)*193 + m0 + mm];
                float c1v = s_ctx[(2*qh+1)*193 + m0 + mm];
                #pragma unroll
                for (int i = 0; i < 12; i++){
                    float wv = s_w[(ng+16*i)*33 + mm];
                    acc0[i] = fmaf(c0v, wv, acc0[i]);
                    acc1[i] = fmaf(c1v, wv, acc1[i]);
                }
            }
        }
        float val0[12], val1[12];
        float s0 = 0.f, s1 = 0.f;
        #pragma unroll
        for (int i = 0; i < 12; i++){
            int n = ng + 16*i;
            val0[i] = acc0[i] + out_b[n] + s_qn[(2*qh)*193 + n];
            val1[i] = acc1[i] + out_b[n] + s_qn[(2*qh+1)*193 + n];
            s0 += val0[i]; s1 += val1[i];
        }
        #pragma unroll
        for (int o = 8; o > 0; o >>= 1){
            s0 += __shfl_xor_sync(0xffffffffu, s0, o);
            s1 += __shfl_xor_sync(0xffffffffu, s1, o);
        }
        float mu0 = s0*(1.f/192.f), mu1 = s1*(1.f/192.f);
        float vs0 = 0.f, vs1 = 0.f;
        #pragma unroll
        for (int i = 0; i < 12; i++){
            float d0 = val0[i]-mu0, d1 = val1[i]-mu1;
            vs0 += d0*d0; vs1 += d1*d1;
        }
        #pragma unroll
        for (int o = 8; o > 0; o >>= 1){
            vs0 += __shfl_xor_sync(0xffffffffu, vs0, o);
            vs1 += __shfl_xor_sync(0xffffffffu, vs1, o);
        }
        float r0 = rsqrtf(vs0*(1.f/192.f) + LN_EPS);
        float r1 = rsqrtf(vs1*(1.f/192.f) + LN_EPS);
        __syncthreads();
        #pragma unroll
        for (int i = 0; i < 12; i++){
            int n = ng + 16*i;
            s_ctx[(2*qh)*193 + n]   = (val0[i]-mu0)*r0*lnow[n] + lnob[n];
            s_ctx[(2*qh+1)*193 + n] = (val1[i]-mu1)*r1*lnow[n] + lnob[n];
        }
    }
    __syncthreads();
    for (int e = t; e < 6144; e += 256){
        int n = e >> 5, q = e & 31;
        out[bp*49152 + n*256 + q0 + q] = s_ctx[q*193 + n];
    }
}

extern "C" void kernel_launch(void* const* d_in, const int* in_sizes, int n_in,
                              void* d_out, int out_size){
    const float* x_p    = (const float*)d_in[0];
    const float* y_g    = (const float*)d_in[1];
    const float* conv1w = (const float*)d_in[2];
    const float* conv1b = (const float*)d_in[3];
    const float* gamma1 = (const float*)d_in[4];
    const float* beta1  = (const float*)d_in[5];
    const float* conv2w = (const float*)d_in[6];
    const float* conv2b = (const float*)d_in[7];
    const float* gamma2 = (const float*)d_in[8];
    const float* beta2  = (const float*)d_in[9];
    const float* conv3w = (const float*)d_in[10];
    const float* conv3b = (const float*)d_in[11];
    const float* lnqw   = (const float*)d_in[12];
    const float* lnqb   = (const float*)d_in[13];
    const float* lnkw   = (const float*)d_in[14];
    const float* lnkb   = (const float*)d_in[15];
    const float* lnow   = (const float*)d_in[16];
    const float* lnob   = (const float*)d_in[17];
    const float* Wq     = (const float*)d_in[18];
    const float* Wk     = (const float*)d_in[19];
    const float* vw     = (const float*)d_in[20];
    const float* Wv     = (const float*)d_in[21];
    const float* outw   = (const float*)d_in[22];
    const float* outb   = (const float*)d_in[23];
    float* out = (float*)d_out;

    cudaFuncSetAttribute(attn_kernel, cudaFuncAttributeMaxDynamicSharedMemorySize, 98304);

    prep_kernel<<<128, 256>>>(gamma1, gamma2);
    conv1_kernel<<<dim3(64,4,2), 256>>>(x_p, conv1w, conv1b);
    gdn_kernel<<<1024, 256>>>(1, beta1);
    conv2_kernel<<<dim3(64,8,2), 128>>>(conv2w, conv2b);
    gdn_kernel<<<256, 256>>>(2, beta2);
    conv3_kernel<<<dim3(64,12,2), 128>>>(conv3w, conv3b);
    kv_kernel<<<dim3(64,5), 256>>>(y_g, lnkw, lnkb, Wk, Wv);
    attn_kernel<<<512, 256, 95872>>>(lnqw, lnqb, Wq, vw, outw, outb, lnow, lnob, out);
}